// round 4
// baseline (speedup 1.0000x reference)
#include <cuda_runtime.h>
#include <cuda_bf16.h>
#include <cstdint>

// Problem constants
#define B_     4
#define NQ     2048
#define DQ     1024
#define NK     1024
#define DC     768
#define HEADS  16
#define DH     64
#define INNER  1024   // HEADS*DH

// ---------------------------------------------------------------------------
// Device scratch (static globals — no allocation allowed)
// ---------------------------------------------------------------------------
__device__ float g_q [(size_t)B_ * NQ * INNER];
__device__ float g_k [(size_t)B_ * NK * INNER];
__device__ float g_v [(size_t)B_ * NK * INNER];
__device__ float g_ao[(size_t)B_ * NQ * INNER];

// bf16 split buffers
__device__ __nv_bfloat16 g_x_hi [(size_t)B_ * NQ * DQ];
__device__ __nv_bfloat16 g_x_lo [(size_t)B_ * NQ * DQ];
__device__ __nv_bfloat16 g_c_hi [(size_t)B_ * NK * DC];
__device__ __nv_bfloat16 g_c_lo [(size_t)B_ * NK * DC];
__device__ __nv_bfloat16 g_ao_hi[(size_t)B_ * NQ * INNER];
__device__ __nv_bfloat16 g_ao_lo[(size_t)B_ * NQ * INNER];
// transposed weights [N,K]
__device__ __nv_bfloat16 g_wqT_hi[(size_t)INNER * DQ];
__device__ __nv_bfloat16 g_wqT_lo[(size_t)INNER * DQ];
__device__ __nv_bfloat16 g_wkT_hi[(size_t)INNER * DC];
__device__ __nv_bfloat16 g_wkT_lo[(size_t)INNER * DC];
__device__ __nv_bfloat16 g_wvT_hi[(size_t)INNER * DC];
__device__ __nv_bfloat16 g_wvT_lo[(size_t)INNER * DC];
__device__ __nv_bfloat16 g_woT_hi[(size_t)DQ * INNER];
__device__ __nv_bfloat16 g_woT_lo[(size_t)DQ * INNER];

// ---------------------------------------------------------------------------
// PTX helpers (sm_80-era only: cp.async, ldmatrix, mma.sync — no tcgen05)
// ---------------------------------------------------------------------------
__device__ __forceinline__ uint32_t smem_u32(const void* p) {
    uint32_t a;
    asm("{ .reg .u64 t; cvta.to.shared.u64 t, %1; cvt.u32.u64 %0, t; }"
        : "=r"(a) : "l"(p));
    return a;
}
__device__ __forceinline__ void cp_async16(uint32_t s, const void* g) {
    asm volatile("cp.async.cg.shared.global [%0], [%1], 16;" :: "r"(s), "l"(g));
}
__device__ __forceinline__ void ldsm_x4(uint32_t* r, uint32_t a) {
    asm volatile("ldmatrix.sync.aligned.m8n8.x4.shared.b16 {%0,%1,%2,%3}, [%4];"
                 : "=r"(r[0]), "=r"(r[1]), "=r"(r[2]), "=r"(r[3]) : "r"(a));
}
__device__ __forceinline__ void mma_bf16(float4& d, const uint32_t a[4],
                                         uint32_t b0, uint32_t b1) {
    asm volatile(
        "mma.sync.aligned.m16n8k16.row.col.f32.bf16.bf16.f32 "
        "{%0,%1,%2,%3}, {%4,%5,%6,%7}, {%8,%9}, {%0,%1,%2,%3};"
        : "+f"(d.x), "+f"(d.y), "+f"(d.z), "+f"(d.w)
        : "r"(a[0]), "r"(a[1]), "r"(a[2]), "r"(a[3]), "r"(b0), "r"(b1));
}
#define SW64(o) ((o) ^ (((o) >> 3) & 0x30))

// ---------------------------------------------------------------------------
// bf16-split GEMM via mma.sync: C[M,N] = (Ah+Al)[M,K] @ (Bh+Bl)^T, B as [N,K].
// 3 terms: AhBh + AhBl + AlBh. CTA tile 128x128x32, 256 thr (8 warps 4x2),
// warp tile 32x64 (2x8 m16n8k16). Double-buffered cp.async, SW64 swizzle.
// ---------------------------------------------------------------------------
#define GTILE_B   8192                 // one 128x32 bf16 tile (row = 64B)
#define GSTAGE_B  (4 * GTILE_B)        // Ah, Al, Bh, Bl
#define GEMM_SMEM (2 * GSTAGE_B)       // 64 KB double buffer

template <bool BIAS>
__global__ __launch_bounds__(256)
void mma_gemm(const __nv_bfloat16* __restrict__ Ah, const __nv_bfloat16* __restrict__ Al,
              const __nv_bfloat16* __restrict__ Bh, const __nv_bfloat16* __restrict__ Bl,
              const float* __restrict__ bias, float* __restrict__ C,
              int M, int N, int K)
{
    extern __shared__ __align__(1024) char smraw[];
    const uint32_t sb = smem_u32(smraw);
    const int tid  = threadIdx.x;
    const int wid  = tid >> 5, lane = tid & 31;
    const int wm   = wid & 3,  wn   = wid >> 2;     // 4 x 2 warp grid
    const int row0 = blockIdx.y * 128, col0 = blockIdx.x * 128;
    const int nch  = K >> 5;

    const int lsel = lane & 15;
    const int kh   = (lane >> 4) * 16;

    float4 acc[2][8];
#pragma unroll
    for (int i = 0; i < 2; i++)
#pragma unroll
        for (int j = 0; j < 8; j++) acc[i][j] = make_float4(0.f, 0.f, 0.f, 0.f);

    const __nv_bfloat16* aH = Ah + (size_t)row0 * K;
    const __nv_bfloat16* aL = Al + (size_t)row0 * K;
    const __nv_bfloat16* bH = Bh + (size_t)col0 * K;
    const __nv_bfloat16* bL = Bl + (size_t)col0 * K;

#define GISSUE(c)                                                              \
    do {                                                                       \
        const uint32_t stg_ = sb + ((c) & 1) * GSTAGE_B;                       \
        const int k0_ = (c) << 5;                                              \
        _Pragma("unroll")                                                      \
        for (int j = 0; j < 8; j++) {                                          \
            const int i_   = tid + 256 * j;                                    \
            const int tile = j >> 1;                                           \
            const int cc   = i_ & 511;                                         \
            const int r    = cc >> 2, cl = cc & 3;                             \
            const uint32_t off = r * 64 + cl * 16;                             \
            const __nv_bfloat16* src =                                         \
                (tile == 0 ? aH : tile == 1 ? aL : tile == 2 ? bH : bL)        \
                + (size_t)r * K + k0_ + cl * 8;                                \
            cp_async16(stg_ + tile * GTILE_B + SW64(off), src);                \
        }                                                                      \
        asm volatile("cp.async.commit_group;" ::: "memory");                   \
    } while (0)

    GISSUE(0);
    for (int c = 0; c < nch; c++) {
        if (c + 1 < nch) {
            GISSUE(c + 1);
            asm volatile("cp.async.wait_group 1;" ::: "memory");
        } else {
            asm volatile("cp.async.wait_group 0;" ::: "memory");
        }
        __syncthreads();

        const uint32_t stg = sb + (c & 1) * GSTAGE_B;
#pragma unroll
        for (int ks = 0; ks < 2; ks++) {
            uint32_t ah[2][4], al[2][4];
#pragma unroll
            for (int mt = 0; mt < 2; mt++) {
                const uint32_t off = (wm * 32 + mt * 16 + lsel) * 64 + ks * 32 + kh;
                ldsm_x4(ah[mt], stg + SW64(off));
                ldsm_x4(al[mt], stg + GTILE_B + SW64(off));
            }
#pragma unroll
            for (int g = 0; g < 4; g++) {
                uint32_t bh[4], bl[4];
                const uint32_t off = (wn * 64 + g * 16 + lsel) * 64 + ks * 32 + kh;
                ldsm_x4(bh, stg + 2 * GTILE_B + SW64(off));
                ldsm_x4(bl, stg + 3 * GTILE_B + SW64(off));
#pragma unroll
                for (int mt = 0; mt < 2; mt++) {
#pragma unroll
                    for (int nt = 0; nt < 2; nt++) {
                        float4& d = acc[mt][g * 2 + nt];
                        mma_bf16(d, ah[mt], bh[nt], bh[2 + nt]);
                        mma_bf16(d, ah[mt], bl[nt], bl[2 + nt]);
                        mma_bf16(d, al[mt], bh[nt], bh[2 + nt]);
                    }
                }
            }
        }
        __syncthreads();
    }
#undef GISSUE

    // Epilogue
    const int rbase = row0 + wm * 32 + (lane >> 2);
    const int cbase = col0 + wn * 64 + (lane & 3) * 2;
#pragma unroll
    for (int mt = 0; mt < 2; mt++) {
#pragma unroll
        for (int nt = 0; nt < 8; nt++) {
            float4 d = acc[mt][nt];
            const int col = cbase + nt * 8;
            float b0 = 0.f, b1 = 0.f;
            if (BIAS) { b0 = bias[col]; b1 = bias[col + 1]; }
            const int r0 = rbase + mt * 16;
            *(float2*)(C + (size_t)r0 * N + col)       = make_float2(d.x + b0, d.y + b1);
            *(float2*)(C + (size_t)(r0 + 8) * N + col) = make_float2(d.z + b0, d.w + b1);
        }
    }
}

// ---------------------------------------------------------------------------
// fp32 -> bf16 hi/lo split (elementwise)
// ---------------------------------------------------------------------------
__global__ void split_kernel(const float4* __restrict__ in,
                             __nv_bfloat162* __restrict__ hi,
                             __nv_bfloat162* __restrict__ lo, int n4)
{
    int i = blockIdx.x * blockDim.x + threadIdx.x;
    if (i >= n4) return;
    float4 v = in[i];
    __nv_bfloat16 h0 = __float2bfloat16(v.x), h1 = __float2bfloat16(v.y);
    __nv_bfloat16 h2 = __float2bfloat16(v.z), h3 = __float2bfloat16(v.w);
    __nv_bfloat16 l0 = __float2bfloat16(v.x - __bfloat162float(h0));
    __nv_bfloat16 l1 = __float2bfloat16(v.y - __bfloat162float(h1));
    __nv_bfloat16 l2 = __float2bfloat16(v.z - __bfloat162float(h2));
    __nv_bfloat16 l3 = __float2bfloat16(v.w - __bfloat162float(h3));
    hi[2 * i]     = __halves2bfloat162(h0, h1);
    hi[2 * i + 1] = __halves2bfloat162(h2, h3);
    lo[2 * i]     = __halves2bfloat162(l0, l1);
    lo[2 * i + 1] = __halves2bfloat162(l2, l3);
}

// fp32 W[K,N] -> bf16 hi/lo transposed [N,K]
__global__ void tsplit_kernel(const float* __restrict__ W,
                              __nv_bfloat16* __restrict__ hiT,
                              __nv_bfloat16* __restrict__ loT, int K, int N)
{
    __shared__ float t[32][33];
    const int n0 = blockIdx.x * 32, k0 = blockIdx.y * 32;
    const int tx = threadIdx.x, ty = threadIdx.y;
#pragma unroll
    for (int j = 0; j < 32; j += 8)
        t[ty + j][tx] = W[(size_t)(k0 + ty + j) * N + n0 + tx];
    __syncthreads();
#pragma unroll
    for (int j = 0; j < 32; j += 8) {
        float x = t[tx][ty + j];
        __nv_bfloat16 h = __float2bfloat16(x);
        __nv_bfloat16 l = __float2bfloat16(x - __bfloat162float(h));
        size_t oidx = (size_t)(n0 + ty + j) * K + k0 + tx;
        hiT[oidx] = h;
        loT[oidx] = l;
    }
}

// ---------------------------------------------------------------------------
// Flash attention (fp32, unchanged from passing baseline)
// ---------------------------------------------------------------------------
#define QS_PITCH 132
#define KS_PITCH 68
#define VS_PITCH 68
#define PS_PITCH 132
#define ATTN_SMEM_FLOATS (64*QS_PITCH + 64*KS_PITCH + 64*VS_PITCH + 64*PS_PITCH)
#define ATTN_SMEM_BYTES  (ATTN_SMEM_FLOATS * 4)

__global__ __launch_bounds__(256)
void attn_kernel(const float* __restrict__ q, const float* __restrict__ kg,
                 const float* __restrict__ vg, float* __restrict__ o)
{
    const int tid = threadIdx.x;
    const int tx  = tid & 15;
    const int ty  = tid >> 4;
    const int q0  = blockIdx.x * 128;
    const int h   = blockIdx.y;
    const int b   = blockIdx.z;

    extern __shared__ float smf[];
    float* Qs = smf;
    float* Ks = Qs + 64 * QS_PITCH;
    float* Vs = Ks + 64 * KS_PITCH;
    float* Ps = Vs + 64 * VS_PITCH;

    const size_t qbase = ((size_t)b * NQ + q0) * INNER + h * DH;
    for (int i = tid; i < 128 * 16; i += 256) {
        int r = i >> 4, c4 = (i & 15) << 2;
        float4 t = *(const float4*)(q + qbase + (size_t)r * INNER + c4);
        Qs[(c4 + 0) * QS_PITCH + r] = t.x;
        Qs[(c4 + 1) * QS_PITCH + r] = t.y;
        Qs[(c4 + 2) * QS_PITCH + r] = t.z;
        Qs[(c4 + 3) * QS_PITCH + r] = t.w;
    }

    float acc[8][4];
    float mrow[8], lrow[8];
#pragma unroll
    for (int i = 0; i < 8; i++) {
        mrow[i] = -1e30f; lrow[i] = 0.0f;
#pragma unroll
        for (int j = 0; j < 4; j++) acc[i][j] = 0.0f;
    }
    const float SCALE = 0.125f;

    for (int kt = 0; kt < NK; kt += 64) {
        __syncthreads();
        const size_t kbase = ((size_t)b * NK + kt) * INNER + h * DH;
        for (int i = tid; i < 64 * 16; i += 256) {
            int key = i >> 4, c4 = (i & 15) << 2;
            float4 t = *(const float4*)(kg + kbase + (size_t)key * INNER + c4);
            Ks[(c4 + 0) * KS_PITCH + key] = t.x;
            Ks[(c4 + 1) * KS_PITCH + key] = t.y;
            Ks[(c4 + 2) * KS_PITCH + key] = t.z;
            Ks[(c4 + 3) * KS_PITCH + key] = t.w;
            float4 u = *(const float4*)(vg + kbase + (size_t)key * INNER + c4);
            *(float4*)&Vs[key * VS_PITCH + c4] = u;
        }
        __syncthreads();

        float s[8][4];
#pragma unroll
        for (int i = 0; i < 8; i++)
#pragma unroll
            for (int j = 0; j < 4; j++) s[i][j] = 0.0f;

#pragma unroll 8
        for (int kk = 0; kk < 64; kk++) {
            float4 a0 = *(const float4*)&Qs[kk * QS_PITCH + ty * 8];
            float4 a1 = *(const float4*)&Qs[kk * QS_PITCH + ty * 8 + 4];
            float4 bk = *(const float4*)&Ks[kk * KS_PITCH + tx * 4];
            float af[8] = {a0.x, a0.y, a0.z, a0.w, a1.x, a1.y, a1.z, a1.w};
            float bf[4] = {bk.x, bk.y, bk.z, bk.w};
#pragma unroll
            for (int i = 0; i < 8; i++)
#pragma unroll
                for (int j = 0; j < 4; j++)
                    s[i][j] = fmaf(af[i], bf[j], s[i][j]);
        }

#pragma unroll
        for (int i = 0; i < 8; i++) {
            float v0 = s[i][0] * SCALE, v1 = s[i][1] * SCALE;
            float v2 = s[i][2] * SCALE, v3 = s[i][3] * SCALE;
            float mx = fmaxf(fmaxf(v0, v1), fmaxf(v2, v3));
#pragma unroll
            for (int off = 8; off >= 1; off >>= 1)
                mx = fmaxf(mx, __shfl_xor_sync(0xffffffffu, mx, off));
            float mnew = fmaxf(mrow[i], mx);
            float corr = __expf(mrow[i] - mnew);
            float p0 = __expf(v0 - mnew), p1 = __expf(v1 - mnew);
            float p2 = __expf(v2 - mnew), p3 = __expf(v3 - mnew);
            float psum = (p0 + p1) + (p2 + p3);
#pragma unroll
            for (int off = 8; off >= 1; off >>= 1)
                psum += __shfl_xor_sync(0xffffffffu, psum, off);
            lrow[i] = lrow[i] * corr + psum;
            mrow[i] = mnew;
            acc[i][0] *= corr; acc[i][1] *= corr;
            acc[i][2] *= corr; acc[i][3] *= corr;
            Ps[(tx * 4 + 0) * PS_PITCH + ty * 8 + i] = p0;
            Ps[(tx * 4 + 1) * PS_PITCH + ty * 8 + i] = p1;
            Ps[(tx * 4 + 2) * PS_PITCH + ty * 8 + i] = p2;
            Ps[(tx * 4 + 3) * PS_PITCH + ty * 8 + i] = p3;
        }
        __syncthreads();

#pragma unroll 8
        for (int key = 0; key < 64; key++) {
            float4 a0 = *(const float4*)&Ps[key * PS_PITCH + ty * 8];
            float4 a1 = *(const float4*)&Ps[key * PS_PITCH + ty * 8 + 4];
            float4 bv = *(const float4*)&Vs[key * VS_PITCH + tx * 4];
            float af[8] = {a0.x, a0.y, a0.z, a0.w, a1.x, a1.y, a1.z, a1.w};
            float bf[4] = {bv.x, bv.y, bv.z, bv.w};
#pragma unroll
            for (int i = 0; i < 8; i++)
#pragma unroll
                for (int j = 0; j < 4; j++)
                    acc[i][j] = fmaf(af[i], bf[j], acc[i][j]);
        }
    }

    const size_t obase = ((size_t)b * NQ + q0) * INNER + h * DH;
#pragma unroll
    for (int i = 0; i < 8; i++) {
        float inv = 1.0f / lrow[i];
        float4 r = make_float4(acc[i][0] * inv, acc[i][1] * inv,
                               acc[i][2] * inv, acc[i][3] * inv);
        *(float4*)(o + obase + (size_t)(ty * 8 + i) * INNER + tx * 4) = r;
    }
}

// ---------------------------------------------------------------------------
// Launch
// ---------------------------------------------------------------------------
extern "C" void kernel_launch(void* const* d_in, const int* in_sizes, int n_in,
                              void* d_out, int out_size)
{
    const float* x   = (const float*)d_in[0];
    const float* ctx = (const float*)d_in[1];
    const float* Wq  = (const float*)d_in[2];
    const float* Wk  = (const float*)d_in[3];
    const float* Wv  = (const float*)d_in[4];
    const float* Wo  = (const float*)d_in[5];
    const float* bo  = (const float*)d_in[6];
    float* out = (float*)d_out;

    float *q, *k, *v, *ao;
    cudaGetSymbolAddress((void**)&q,  g_q);
    cudaGetSymbolAddress((void**)&k,  g_k);
    cudaGetSymbolAddress((void**)&v,  g_v);
    cudaGetSymbolAddress((void**)&ao, g_ao);
    __nv_bfloat16 *xh, *xl, *ch, *cl, *aoh, *aol;
    __nv_bfloat16 *wqh, *wql, *wkh, *wkl, *wvh, *wvl, *woh, *wol;
    cudaGetSymbolAddress((void**)&xh,  g_x_hi);  cudaGetSymbolAddress((void**)&xl,  g_x_lo);
    cudaGetSymbolAddress((void**)&ch,  g_c_hi);  cudaGetSymbolAddress((void**)&cl,  g_c_lo);
    cudaGetSymbolAddress((void**)&aoh, g_ao_hi); cudaGetSymbolAddress((void**)&aol, g_ao_lo);
    cudaGetSymbolAddress((void**)&wqh, g_wqT_hi); cudaGetSymbolAddress((void**)&wql, g_wqT_lo);
    cudaGetSymbolAddress((void**)&wkh, g_wkT_hi); cudaGetSymbolAddress((void**)&wkl, g_wkT_lo);
    cudaGetSymbolAddress((void**)&wvh, g_wvT_hi); cudaGetSymbolAddress((void**)&wvl, g_wvT_lo);
    cudaGetSymbolAddress((void**)&woh, g_woT_hi); cudaGetSymbolAddress((void**)&wol, g_woT_lo);

    cudaFuncSetAttribute(attn_kernel, cudaFuncAttributeMaxDynamicSharedMemorySize,
                         ATTN_SMEM_BYTES);
    cudaFuncSetAttribute(mma_gemm<false>, cudaFuncAttributeMaxDynamicSharedMemorySize,
                         GEMM_SMEM);
    cudaFuncSetAttribute(mma_gemm<true>, cudaFuncAttributeMaxDynamicSharedMemorySize,
                         GEMM_SMEM);

    // Splits
    {
        int n4 = (B_ * NQ * DQ) / 4;
        split_kernel<<<(n4 + 255) / 256, 256>>>((const float4*)x,
            (__nv_bfloat162*)xh, (__nv_bfloat162*)xl, n4);
    }
    {
        int n4 = (B_ * NK * DC) / 4;
        split_kernel<<<(n4 + 255) / 256, 256>>>((const float4*)ctx,
            (__nv_bfloat162*)ch, (__nv_bfloat162*)cl, n4);
    }
    tsplit_kernel<<<dim3(INNER / 32, DQ / 32), dim3(32, 8)>>>(Wq, wqh, wql, DQ, INNER);
    tsplit_kernel<<<dim3(INNER / 32, DC / 32), dim3(32, 8)>>>(Wk, wkh, wkl, DC, INNER);
    tsplit_kernel<<<dim3(INNER / 32, DC / 32), dim3(32, 8)>>>(Wv, wvh, wvl, DC, INNER);
    tsplit_kernel<<<dim3(DQ / 32, INNER / 32), dim3(32, 8)>>>(Wo, woh, wol, INNER, DQ);

    // Projections (tensor cores via mma.sync)
    mma_gemm<false><<<dim3(INNER / 128, (B_ * NQ) / 128), 256, GEMM_SMEM>>>(
        xh, xl, wqh, wql, nullptr, q, B_ * NQ, INNER, DQ);
    mma_gemm<false><<<dim3(INNER / 128, (B_ * NK) / 128), 256, GEMM_SMEM>>>(
        ch, cl, wkh, wkl, nullptr, k, B_ * NK, INNER, DC);
    mma_gemm<false><<<dim3(INNER / 128, (B_ * NK) / 128), 256, GEMM_SMEM>>>(
        ch, cl, wvh, wvl, nullptr, v, B_ * NK, INNER, DC);

    // Attention (fp32)
    attn_kernel<<<dim3(NQ / 128, HEADS, B_), 256, ATTN_SMEM_BYTES>>>(q, k, v, ao);

    // Output projection
    {
        int n4 = (B_ * NQ * INNER) / 4;
        split_kernel<<<(n4 + 255) / 256, 256>>>((const float4*)ao,
            (__nv_bfloat162*)aoh, (__nv_bfloat162*)aol, n4);
    }
    mma_gemm<true><<<dim3(DQ / 128, (B_ * NQ) / 128), 256, GEMM_SMEM>>>(
        aoh, aol, woh, wol, bo, out, B_ * NQ, DQ, INNER);
}

// round 5
// speedup vs baseline: 2.5092x; 2.5092x over previous
#include <cuda_runtime.h>
#include <cuda_bf16.h>
#include <cstdint>

// Problem constants
#define B_     4
#define NQ     2048
#define DQ     1024
#define NK     1024
#define DC     768
#define HEADS  16
#define DH     64
#define INNER  1024   // HEADS*DH

// ---------------------------------------------------------------------------
// Device scratch (static globals — no allocation allowed). All bf16 hi/lo.
// ---------------------------------------------------------------------------
__device__ __nv_bfloat16 g_x_hi [(size_t)B_ * NQ * DQ];
__device__ __nv_bfloat16 g_x_lo [(size_t)B_ * NQ * DQ];
__device__ __nv_bfloat16 g_c_hi [(size_t)B_ * NK * DC];
__device__ __nv_bfloat16 g_c_lo [(size_t)B_ * NK * DC];
__device__ __nv_bfloat16 g_q_hi [(size_t)B_ * NQ * INNER];
__device__ __nv_bfloat16 g_q_lo [(size_t)B_ * NQ * INNER];
__device__ __nv_bfloat16 g_k_hi [(size_t)B_ * NK * INNER];
__device__ __nv_bfloat16 g_k_lo [(size_t)B_ * NK * INNER];
__device__ __nv_bfloat16 g_v_hi [(size_t)B_ * NK * INNER];
__device__ __nv_bfloat16 g_v_lo [(size_t)B_ * NK * INNER];
__device__ __nv_bfloat16 g_ao_hi[(size_t)B_ * NQ * INNER];
__device__ __nv_bfloat16 g_ao_lo[(size_t)B_ * NQ * INNER];
// transposed weights [N,K]
__device__ __nv_bfloat16 g_wqT_hi[(size_t)INNER * DQ];
__device__ __nv_bfloat16 g_wqT_lo[(size_t)INNER * DQ];
__device__ __nv_bfloat16 g_wkT_hi[(size_t)INNER * DC];
__device__ __nv_bfloat16 g_wkT_lo[(size_t)INNER * DC];
__device__ __nv_bfloat16 g_wvT_hi[(size_t)INNER * DC];
__device__ __nv_bfloat16 g_wvT_lo[(size_t)INNER * DC];
__device__ __nv_bfloat16 g_woT_hi[(size_t)DQ * INNER];
__device__ __nv_bfloat16 g_woT_lo[(size_t)DQ * INNER];

// ---------------------------------------------------------------------------
// PTX helpers (sm_80-era only: cp.async, ldmatrix, mma.sync)
// ---------------------------------------------------------------------------
__device__ __forceinline__ uint32_t smem_u32(const void* p) {
    uint32_t a;
    asm("{ .reg .u64 t; cvta.to.shared.u64 t, %1; cvt.u32.u64 %0, t; }"
        : "=r"(a) : "l"(p));
    return a;
}
__device__ __forceinline__ void cp_async16(uint32_t s, const void* g) {
    asm volatile("cp.async.cg.shared.global [%0], [%1], 16;" :: "r"(s), "l"(g));
}
__device__ __forceinline__ void ldsm_x4(uint32_t* r, uint32_t a) {
    asm volatile("ldmatrix.sync.aligned.m8n8.x4.shared.b16 {%0,%1,%2,%3}, [%4];"
                 : "=r"(r[0]), "=r"(r[1]), "=r"(r[2]), "=r"(r[3]) : "r"(a));
}
__device__ __forceinline__ void ldsm_x4_t(uint32_t* r, uint32_t a) {
    asm volatile("ldmatrix.sync.aligned.m8n8.x4.trans.shared.b16 {%0,%1,%2,%3}, [%4];"
                 : "=r"(r[0]), "=r"(r[1]), "=r"(r[2]), "=r"(r[3]) : "r"(a));
}
__device__ __forceinline__ void mma_bf16(float* d, const uint32_t a[4],
                                         uint32_t b0, uint32_t b1) {
    asm volatile(
        "mma.sync.aligned.m16n8k16.row.col.f32.bf16.bf16.f32 "
        "{%0,%1,%2,%3}, {%4,%5,%6,%7}, {%8,%9}, {%0,%1,%2,%3};"
        : "+f"(d[0]), "+f"(d[1]), "+f"(d[2]), "+f"(d[3])
        : "r"(a[0]), "r"(a[1]), "r"(a[2]), "r"(a[3]), "r"(b0), "r"(b1));
}
#define SW64(o)  ((o) ^ (((o) >> 3) & 0x30))
#define SW128(o) ((o) ^ (((o) >> 3) & 0x70))
#define CP_COMMIT() asm volatile("cp.async.commit_group;" ::: "memory")
#define CP_WAIT0()  asm volatile("cp.async.wait_group 0;" ::: "memory")
#define CP_WAIT1()  asm volatile("cp.async.wait_group 1;" ::: "memory")

__device__ __forceinline__ uint32_t pack_bf(float a, float b) {
    __nv_bfloat162 t = __halves2bfloat162(__float2bfloat16(a), __float2bfloat16(b));
    return *(uint32_t*)&t;
}
__device__ __forceinline__ uint32_t pack_bf_lo(float a, float b, uint32_t hp) {
    __nv_bfloat162 h = *(__nv_bfloat162*)&hp;
    return pack_bf(a - __bfloat162float(h.x), b - __bfloat162float(h.y));
}
__device__ __forceinline__ void store_split(__nv_bfloat16* H, __nv_bfloat16* L,
                                            size_t idx, float a, float b) {
    uint32_t hp = pack_bf(a, b);
    uint32_t lp = pack_bf_lo(a, b, hp);
    *(uint32_t*)(H + idx) = hp;
    *(uint32_t*)(L + idx) = lp;
}

// ---------------------------------------------------------------------------
// bf16-split GEMM via mma.sync: C = (Ah+Al)[M,K] @ (Bh+Bl)^T, B given [N,K].
// 3 terms term-major (acc reuse distance 16). CTA 128x128x32, 8 warps (4x2),
// 3-stage cp.async ring, SW64 smem. MODE 0: hi/lo bf16 out; MODE 1: f32+bias.
// ---------------------------------------------------------------------------
#define GTILE_B   8192                 // one 128x32 bf16 tile (row = 64B)
#define GSTAGE_B  (4 * GTILE_B)        // Ah, Al, Bh, Bl
#define GEMM_SMEM (3 * GSTAGE_B)       // 96 KB, 3-stage ring

template <int MODE>
__global__ __launch_bounds__(256)
void mma_gemm(const __nv_bfloat16* __restrict__ Ah, const __nv_bfloat16* __restrict__ Al,
              const __nv_bfloat16* __restrict__ Bh, const __nv_bfloat16* __restrict__ Bl,
              const float* __restrict__ bias, float* __restrict__ Cf,
              __nv_bfloat16* __restrict__ Ch, __nv_bfloat16* __restrict__ Cl,
              int M, int N, int K)
{
    extern __shared__ __align__(1024) char smraw[];
    const uint32_t sb = smem_u32(smraw);
    const int tid  = threadIdx.x;
    const int wid  = tid >> 5, lane = tid & 31;
    const int wm   = wid & 3,  wn   = wid >> 2;     // 4 x 2 warp grid
    const int row0 = blockIdx.y * 128, col0 = blockIdx.x * 128;
    const int nch  = K >> 5;
    const int lsel = lane & 15;
    const int khf  = (lane >> 4) * 16;

    float acc[2][8][4];
#pragma unroll
    for (int i = 0; i < 2; i++)
#pragma unroll
        for (int j = 0; j < 8; j++)
#pragma unroll
            for (int q = 0; q < 4; q++) acc[i][j][q] = 0.f;

    const __nv_bfloat16* aH = Ah + (size_t)row0 * K;
    const __nv_bfloat16* aL = Al + (size_t)row0 * K;
    const __nv_bfloat16* bH = Bh + (size_t)col0 * K;
    const __nv_bfloat16* bL = Bl + (size_t)col0 * K;

#define GISSUE(c)                                                              \
    do {                                                                       \
        const uint32_t stg_ = sb + ((c) % 3) * GSTAGE_B;                       \
        const int k0_ = (c) << 5;                                              \
        _Pragma("unroll")                                                      \
        for (int j = 0; j < 8; j++) {                                          \
            const int i_   = tid + 256 * j;                                    \
            const int tile = j >> 1;                                           \
            const int cc   = i_ & 511;                                         \
            const int r    = cc >> 2, cl = cc & 3;                             \
            const uint32_t off = r * 64 + cl * 16;                             \
            const __nv_bfloat16* src =                                         \
                (tile == 0 ? aH : tile == 1 ? aL : tile == 2 ? bH : bL)        \
                + (size_t)r * K + k0_ + cl * 8;                                \
            cp_async16(stg_ + tile * GTILE_B + SW64(off), src);                \
        }                                                                      \
        CP_COMMIT();                                                           \
    } while (0)

    GISSUE(0);
    GISSUE(1);
    for (int c = 0; c < nch; c++) {
        if (c + 1 < nch) { CP_WAIT1(); } else { CP_WAIT0(); }
        __syncthreads();
        if (c + 2 < nch) GISSUE(c + 2);

        const uint32_t stg = sb + (c % 3) * GSTAGE_B;
#pragma unroll
        for (int ks = 0; ks < 2; ks++) {
            uint32_t ah[2][4], al[2][4], bh[4][4], bl[4][4];
#pragma unroll
            for (int mt = 0; mt < 2; mt++) {
                const uint32_t off = (wm * 32 + mt * 16 + lsel) * 64 + ks * 32 + khf;
                ldsm_x4(ah[mt], stg + SW64(off));
                ldsm_x4(al[mt], stg + GTILE_B + SW64(off));
            }
#pragma unroll
            for (int g = 0; g < 4; g++) {
                const uint32_t off = (wn * 64 + g * 16 + lsel) * 64 + ks * 32 + khf;
                ldsm_x4(bh[g], stg + 2 * GTILE_B + SW64(off));
                ldsm_x4(bl[g], stg + 3 * GTILE_B + SW64(off));
            }
            // term-major: same-acc reuse distance = 16 MMAs
#pragma unroll
            for (int g = 0; g < 4; g++)
#pragma unroll
                for (int mt = 0; mt < 2; mt++)
#pragma unroll
                    for (int nt = 0; nt < 2; nt++)
                        mma_bf16(acc[mt][g * 2 + nt], ah[mt], bh[g][nt], bh[g][2 + nt]);
#pragma unroll
            for (int g = 0; g < 4; g++)
#pragma unroll
                for (int mt = 0; mt < 2; mt++)
#pragma unroll
                    for (int nt = 0; nt < 2; nt++)
                        mma_bf16(acc[mt][g * 2 + nt], ah[mt], bl[g][nt], bl[g][2 + nt]);
#pragma unroll
            for (int g = 0; g < 4; g++)
#pragma unroll
                for (int mt = 0; mt < 2; mt++)
#pragma unroll
                    for (int nt = 0; nt < 2; nt++)
                        mma_bf16(acc[mt][g * 2 + nt], al[mt], bh[g][nt], bh[g][2 + nt]);
        }
    }
#undef GISSUE

    // Epilogue
    const int rb = row0 + wm * 32 + (lane >> 2);
    const int cb = col0 + wn * 64 + (lane & 3) * 2;
#pragma unroll
    for (int mt = 0; mt < 2; mt++) {
#pragma unroll
        for (int j = 0; j < 8; j++) {
            const int col = cb + j * 8;
            const int r0 = rb + mt * 16;
            float d0 = acc[mt][j][0], d1 = acc[mt][j][1];
            float d2 = acc[mt][j][2], d3 = acc[mt][j][3];
            if (MODE == 1) {
                float b0 = bias[col], b1 = bias[col + 1];
                *(float2*)(Cf + (size_t)r0 * N + col)       = make_float2(d0 + b0, d1 + b1);
                *(float2*)(Cf + (size_t)(r0 + 8) * N + col) = make_float2(d2 + b0, d3 + b1);
            } else {
                store_split(Ch, Cl, (size_t)r0 * N + col, d0, d1);
                store_split(Ch, Cl, (size_t)(r0 + 8) * N + col, d2, d3);
            }
        }
    }
}

// ---------------------------------------------------------------------------
// Flash attention via mma.sync, bf16 3-term split, FA2-style.
// CTA: 128 q-rows x one head x one batch; 8 warps, each warp 16 rows.
// K/V hi/lo tiles of 64 keys, 3-stage cp.async ring. Outputs ao hi/lo bf16.
// ---------------------------------------------------------------------------
#define AQ_H 0
#define AQ_L 16384
#define AR_BASE  32768
#define AR_STAGE 32768
#define AK_H 0
#define AK_L 8192
#define AV_H 16384
#define AV_L 24576
#define ATTN_SMEM (32768 + 3 * 32768)   // 128 KB

__global__ __launch_bounds__(256)
void attn_mma(const __nv_bfloat16* __restrict__ qh, const __nv_bfloat16* __restrict__ ql,
              const __nv_bfloat16* __restrict__ kh, const __nv_bfloat16* __restrict__ kl,
              const __nv_bfloat16* __restrict__ vh, const __nv_bfloat16* __restrict__ vl,
              __nv_bfloat16* __restrict__ aoh, __nv_bfloat16* __restrict__ aol)
{
    extern __shared__ __align__(1024) char smraw[];
    const uint32_t sb = smem_u32(smraw);
    const int tid = threadIdx.x, lane = tid & 31, w = tid >> 5;
    const int q0 = blockIdx.x * 128;
    const int h  = blockIdx.y;
    const int b  = blockIdx.z;
    const int lsel = lane & 15;
    const int khf  = (lane >> 4) * 16;
    const float SCALE = 0.125f;

    // Load Q tile (hi/lo) into smem, SW128 swizzle (row pitch 128B)
    const size_t qgb = ((size_t)b * NQ + q0) * INNER + h * DH;
#pragma unroll
    for (int j = 0; j < 8; j++) {
        int idx = tid + 256 * j;           // 0..2047
        int bq  = idx >> 10;               // 0: hi, 1: lo
        int cc  = idx & 1023;
        int r = cc >> 3, seg = cc & 7;
        uint32_t off = r * 128 + seg * 16;
        const __nv_bfloat16* src = (bq ? ql : qh) + qgb + (size_t)r * INNER + seg * 8;
        *(float4*)(smraw + (bq ? AQ_L : AQ_H) + SW128(off)) = *(const float4*)src;
    }
    __syncthreads();

    // Preload Q A-fragments (rows 16w..16w+15, 4 ksteps over dh=64)
    uint32_t qfh[4][4], qfl[4][4];
#pragma unroll
    for (int ks = 0; ks < 4; ks++) {
        uint32_t off = (w * 16 + lsel) * 128 + ks * 32 + khf;
        ldsm_x4(qfh[ks], sb + AQ_H + SW128(off));
        ldsm_x4(qfl[ks], sb + AQ_L + SW128(off));
    }

    float oacc[8][4];
#pragma unroll
    for (int j = 0; j < 8; j++)
#pragma unroll
        for (int q = 0; q < 4; q++) oacc[j][q] = 0.f;
    float m0 = -1e30f, m1 = -1e30f, l0 = 0.f, l1 = 0.f;

#define AT_ISSUE(kt)                                                           \
    do {                                                                       \
        const uint32_t stg_ = sb + AR_BASE + ((kt) % 3) * AR_STAGE;            \
        const size_t kvg = ((size_t)b * NK + (kt) * 64) * INNER + h * DH;      \
        _Pragma("unroll")                                                      \
        for (int j = 0; j < 8; j++) {                                          \
            int idx = tid + 256 * j;                                           \
            int buf = idx >> 9;            /* 0:kh 1:kl 2:vh 3:vl */           \
            int cc  = idx & 511;                                               \
            int r = cc >> 3, seg = cc & 7;                                     \
            uint32_t off = r * 128 + seg * 16;                                 \
            const __nv_bfloat16* src =                                         \
                (buf == 0 ? kh : buf == 1 ? kl : buf == 2 ? vh : vl)           \
                + kvg + (size_t)r * INNER + seg * 8;                           \
            cp_async16(stg_ + buf * 8192 + SW128(off), src);                   \
        }                                                                      \
        CP_COMMIT();                                                           \
    } while (0)

    const int NT = NK / 64;   // 16
    AT_ISSUE(0);
    AT_ISSUE(1);
    for (int kt = 0; kt < NT; kt++) {
        if (kt + 1 < NT) { CP_WAIT1(); } else { CP_WAIT0(); }
        __syncthreads();
        if (kt + 2 < NT) AT_ISSUE(kt + 2);
        const uint32_t stg = sb + AR_BASE + (kt % 3) * AR_STAGE;

        // ---- S = Q @ K^T : 16 rows x 64 keys per warp ----
        float sacc[8][4];
#pragma unroll
        for (int j = 0; j < 8; j++)
#pragma unroll
            for (int q = 0; q < 4; q++) sacc[j][q] = 0.f;

#pragma unroll
        for (int ks = 0; ks < 4; ks++) {
            uint32_t bh[4][4], bl[4][4];
#pragma unroll
            for (int g = 0; g < 4; g++) {
                uint32_t off = (g * 16 + lsel) * 128 + ks * 32 + khf;
                ldsm_x4(bh[g], stg + AK_H + SW128(off));
                ldsm_x4(bl[g], stg + AK_L + SW128(off));
            }
#pragma unroll
            for (int g = 0; g < 4; g++)
#pragma unroll
                for (int nt = 0; nt < 2; nt++)
                    mma_bf16(sacc[g * 2 + nt], qfh[ks], bh[g][nt], bh[g][2 + nt]);
#pragma unroll
            for (int g = 0; g < 4; g++)
#pragma unroll
                for (int nt = 0; nt < 2; nt++)
                    mma_bf16(sacc[g * 2 + nt], qfh[ks], bl[g][nt], bl[g][2 + nt]);
#pragma unroll
            for (int g = 0; g < 4; g++)
#pragma unroll
                for (int nt = 0; nt < 2; nt++)
                    mma_bf16(sacc[g * 2 + nt], qfl[ks], bh[g][nt], bh[g][2 + nt]);
        }

        // ---- online softmax (rows r0 = lane>>2, r1 = r0+8 of warp tile) ----
        float rx0 = -1e30f, rx1 = -1e30f;
#pragma unroll
        for (int j = 0; j < 8; j++) {
            rx0 = fmaxf(rx0, fmaxf(sacc[j][0], sacc[j][1]));
            rx1 = fmaxf(rx1, fmaxf(sacc[j][2], sacc[j][3]));
        }
#pragma unroll
        for (int off = 1; off <= 2; off <<= 1) {
            rx0 = fmaxf(rx0, __shfl_xor_sync(0xffffffffu, rx0, off));
            rx1 = fmaxf(rx1, __shfl_xor_sync(0xffffffffu, rx1, off));
        }
        float nm0 = fmaxf(m0, rx0 * SCALE), nm1 = fmaxf(m1, rx1 * SCALE);
        float c0 = __expf(m0 - nm0), c1 = __expf(m1 - nm1);
        m0 = nm0; m1 = nm1;

        float ps0 = 0.f, ps1 = 0.f;
        uint32_t pah[4][4], pal[4][4];
#pragma unroll
        for (int t = 0; t < 4; t++) {
#pragma unroll
            for (int jj = 0; jj < 2; jj++) {
                int j = 2 * t + jj;
                float p00 = __expf(fmaf(sacc[j][0], SCALE, -nm0));
                float p01 = __expf(fmaf(sacc[j][1], SCALE, -nm0));
                float p10 = __expf(fmaf(sacc[j][2], SCALE, -nm1));
                float p11 = __expf(fmaf(sacc[j][3], SCALE, -nm1));
                ps0 += p00 + p01;
                ps1 += p10 + p11;
                uint32_t h0 = pack_bf(p00, p01), h1 = pack_bf(p10, p11);
                pah[t][jj * 2]     = h0;
                pah[t][jj * 2 + 1] = h1;
                pal[t][jj * 2]     = pack_bf_lo(p00, p01, h0);
                pal[t][jj * 2 + 1] = pack_bf_lo(p10, p11, h1);
            }
        }
#pragma unroll
        for (int off = 1; off <= 2; off <<= 1) {
            ps0 += __shfl_xor_sync(0xffffffffu, ps0, off);
            ps1 += __shfl_xor_sync(0xffffffffu, ps1, off);
        }
        l0 = l0 * c0 + ps0;
        l1 = l1 * c1 + ps1;
#pragma unroll
        for (int j = 0; j < 8; j++) {
            oacc[j][0] *= c0; oacc[j][1] *= c0;
            oacc[j][2] *= c1; oacc[j][3] *= c1;
        }

        // ---- O += P @ V : B = V^T via ldmatrix.trans ----
        const int tt = lane >> 3;
#pragma unroll
        for (int t = 0; t < 4; t++) {
            uint32_t vbh[4][4], vbl[4][4];
#pragma unroll
            for (int g = 0; g < 4; g++) {
                uint32_t off = (t * 16 + (lane & 7) + (tt >> 1) * 8) * 128
                               + g * 32 + (tt & 1) * 16;
                ldsm_x4_t(vbh[g], stg + AV_H + SW128(off));
                ldsm_x4_t(vbl[g], stg + AV_L + SW128(off));
            }
#pragma unroll
            for (int g = 0; g < 4; g++)
#pragma unroll
                for (int nt = 0; nt < 2; nt++)
                    mma_bf16(oacc[g * 2 + nt], pah[t], vbh[g][nt], vbh[g][2 + nt]);
#pragma unroll
            for (int g = 0; g < 4; g++)
#pragma unroll
                for (int nt = 0; nt < 2; nt++)
                    mma_bf16(oacc[g * 2 + nt], pah[t], vbl[g][nt], vbl[g][2 + nt]);
#pragma unroll
            for (int g = 0; g < 4; g++)
#pragma unroll
                for (int nt = 0; nt < 2; nt++)
                    mma_bf16(oacc[g * 2 + nt], pal[t], vbh[g][nt], vbh[g][2 + nt]);
        }
    }
#undef AT_ISSUE

    // Epilogue: normalize, split to bf16 hi/lo
    const float inv0 = 1.f / l0, inv1 = 1.f / l1;
    const int r0g = q0 + w * 16 + (lane >> 2);
    const int r1g = r0g + 8;
    const int cbase = h * DH + (lane & 3) * 2;
#pragma unroll
    for (int j = 0; j < 8; j++) {
        const int col = cbase + j * 8;
        store_split(aoh, aol, ((size_t)b * NQ + r0g) * INNER + col,
                    oacc[j][0] * inv0, oacc[j][1] * inv0);
        store_split(aoh, aol, ((size_t)b * NQ + r1g) * INNER + col,
                    oacc[j][2] * inv1, oacc[j][3] * inv1);
    }
}

// ---------------------------------------------------------------------------
// Fused fp32 -> bf16 hi/lo split for x and ctx (one launch)
// ---------------------------------------------------------------------------
__global__ void split2_kernel(const float4* __restrict__ inA,
                              __nv_bfloat162* __restrict__ hA,
                              __nv_bfloat162* __restrict__ lA, int n4A,
                              const float4* __restrict__ inB,
                              __nv_bfloat162* __restrict__ hB,
                              __nv_bfloat162* __restrict__ lB, int n4B)
{
    int i = blockIdx.x * blockDim.x + threadIdx.x;
    const float4* in;
    __nv_bfloat162 *hi, *lo;
    int idx;
    if (i < n4A) { in = inA; hi = hA; lo = lA; idx = i; }
    else { idx = i - n4A; if (idx >= n4B) return; in = inB; hi = hB; lo = lB; }
    float4 v = in[idx];
    __nv_bfloat16 h0 = __float2bfloat16(v.x), h1 = __float2bfloat16(v.y);
    __nv_bfloat16 h2 = __float2bfloat16(v.z), h3 = __float2bfloat16(v.w);
    hi[2 * idx]     = __halves2bfloat162(h0, h1);
    hi[2 * idx + 1] = __halves2bfloat162(h2, h3);
    lo[2 * idx]     = __halves2bfloat162(
        __float2bfloat16(v.x - __bfloat162float(h0)),
        __float2bfloat16(v.y - __bfloat162float(h1)));
    lo[2 * idx + 1] = __halves2bfloat162(
        __float2bfloat16(v.z - __bfloat162float(h2)),
        __float2bfloat16(v.w - __bfloat162float(h3)));
}

// fp32 W[K,N] -> bf16 hi/lo transposed [N,K]
__global__ void tsplit_kernel(const float* __restrict__ W,
                              __nv_bfloat16* __restrict__ hiT,
                              __nv_bfloat16* __restrict__ loT, int K, int N)
{
    __shared__ float t[32][33];
    const int n0 = blockIdx.x * 32, k0 = blockIdx.y * 32;
    const int tx = threadIdx.x, ty = threadIdx.y;
#pragma unroll
    for (int j = 0; j < 32; j += 8)
        t[ty + j][tx] = W[(size_t)(k0 + ty + j) * N + n0 + tx];
    __syncthreads();
#pragma unroll
    for (int j = 0; j < 32; j += 8) {
        float x = t[tx][ty + j];
        __nv_bfloat16 h = __float2bfloat16(x);
        __nv_bfloat16 l = __float2bfloat16(x - __bfloat162float(h));
        size_t oidx = (size_t)(n0 + ty + j) * K + k0 + tx;
        hiT[oidx] = h;
        loT[oidx] = l;
    }
}

// ---------------------------------------------------------------------------
// Launch
// ---------------------------------------------------------------------------
extern "C" void kernel_launch(void* const* d_in, const int* in_sizes, int n_in,
                              void* d_out, int out_size)
{
    const float* x   = (const float*)d_in[0];
    const float* ctx = (const float*)d_in[1];
    const float* Wq  = (const float*)d_in[2];
    const float* Wk  = (const float*)d_in[3];
    const float* Wv  = (const float*)d_in[4];
    const float* Wo  = (const float*)d_in[5];
    const float* bo  = (const float*)d_in[6];
    float* out = (float*)d_out;

    __nv_bfloat16 *xh, *xl, *ch, *cl;
    __nv_bfloat16 *qhp, *qlp, *khp, *klp, *vhp, *vlp, *aoh, *aol;
    __nv_bfloat16 *wqh, *wql, *wkh, *wkl, *wvh, *wvl, *woh, *wol;
    cudaGetSymbolAddress((void**)&xh,  g_x_hi);  cudaGetSymbolAddress((void**)&xl,  g_x_lo);
    cudaGetSymbolAddress((void**)&ch,  g_c_hi);  cudaGetSymbolAddress((void**)&cl,  g_c_lo);
    cudaGetSymbolAddress((void**)&qhp, g_q_hi);  cudaGetSymbolAddress((void**)&qlp, g_q_lo);
    cudaGetSymbolAddress((void**)&khp, g_k_hi);  cudaGetSymbolAddress((void**)&klp, g_k_lo);
    cudaGetSymbolAddress((void**)&vhp, g_v_hi);  cudaGetSymbolAddress((void**)&vlp, g_v_lo);
    cudaGetSymbolAddress((void**)&aoh, g_ao_hi); cudaGetSymbolAddress((void**)&aol, g_ao_lo);
    cudaGetSymbolAddress((void**)&wqh, g_wqT_hi); cudaGetSymbolAddress((void**)&wql, g_wqT_lo);
    cudaGetSymbolAddress((void**)&wkh, g_wkT_hi); cudaGetSymbolAddress((void**)&wkl, g_wkT_lo);
    cudaGetSymbolAddress((void**)&wvh, g_wvT_hi); cudaGetSymbolAddress((void**)&wvl, g_wvT_lo);
    cudaGetSymbolAddress((void**)&woh, g_woT_hi); cudaGetSymbolAddress((void**)&wol, g_woT_lo);

    cudaFuncSetAttribute(mma_gemm<0>, cudaFuncAttributeMaxDynamicSharedMemorySize, GEMM_SMEM);
    cudaFuncSetAttribute(mma_gemm<1>, cudaFuncAttributeMaxDynamicSharedMemorySize, GEMM_SMEM);
    cudaFuncSetAttribute(attn_mma, cudaFuncAttributeMaxDynamicSharedMemorySize, ATTN_SMEM);

    // 1 launch: fused splits of x and ctx
    {
        int n4A = (B_ * NQ * DQ) / 4, n4B = (B_ * NK * DC) / 4;
        int tot = n4A + n4B;
        split2_kernel<<<(tot + 255) / 256, 256>>>(
            (const float4*)x, (__nv_bfloat162*)xh, (__nv_bfloat162*)xl, n4A,
            (const float4*)ctx, (__nv_bfloat162*)ch, (__nv_bfloat162*)cl, n4B);
    }
    // 4 launches: weight transpose+split
    tsplit_kernel<<<dim3(INNER / 32, DQ / 32), dim3(32, 8)>>>(Wq, wqh, wql, DQ, INNER);
    tsplit_kernel<<<dim3(INNER / 32, DC / 32), dim3(32, 8)>>>(Wk, wkh, wkl, DC, INNER);
    tsplit_kernel<<<dim3(INNER / 32, DC / 32), dim3(32, 8)>>>(Wv, wvh, wvl, DC, INNER);
    tsplit_kernel<<<dim3(DQ / 32, INNER / 32), dim3(32, 8)>>>(Wo, woh, wol, INNER, DQ);

    // Projections -> bf16 hi/lo outputs (launch #6 = Q proj, profiled by ncu)
    mma_gemm<0><<<dim3(INNER / 128, (B_ * NQ) / 128), 256, GEMM_SMEM>>>(
        xh, xl, wqh, wql, nullptr, nullptr, qhp, qlp, B_ * NQ, INNER, DQ);
    mma_gemm<0><<<dim3(INNER / 128, (B_ * NK) / 128), 256, GEMM_SMEM>>>(
        ch, cl, wkh, wkl, nullptr, nullptr, khp, klp, B_ * NK, INNER, DC);
    mma_gemm<0><<<dim3(INNER / 128, (B_ * NK) / 128), 256, GEMM_SMEM>>>(
        ch, cl, wvh, wvl, nullptr, nullptr, vhp, vlp, B_ * NK, INNER, DC);

    // Attention (tensor cores) -> ao hi/lo
    attn_mma<<<dim3(NQ / 128, HEADS, B_), 256, ATTN_SMEM>>>(
        qhp, qlp, khp, klp, vhp, vlp, aoh, aol);

    // Output projection -> fp32 + bias
    mma_gemm<1><<<dim3(DQ / 128, (B_ * NQ) / 128), 256, GEMM_SMEM>>>(
        aoh, aol, woh, wol, bo, out, nullptr, nullptr, B_ * NQ, DQ, INNER);
}

// round 6
// speedup vs baseline: 2.5216x; 1.0050x over previous
#include <cuda_runtime.h>
#include <cuda_bf16.h>
#include <cstdint>

// Problem constants
#define B_     4
#define NQ     2048
#define DQ     1024
#define NK     1024
#define DC     768
#define HEADS  16
#define DH     64
#define INNER  1024   // HEADS*DH

// ---------------------------------------------------------------------------
// Device scratch (static globals). All bf16 hi/lo. Weights kept NATURAL [K,N].
// ---------------------------------------------------------------------------
__device__ __nv_bfloat16 g_x_hi [(size_t)B_ * NQ * DQ];
__device__ __nv_bfloat16 g_x_lo [(size_t)B_ * NQ * DQ];
__device__ __nv_bfloat16 g_c_hi [(size_t)B_ * NK * DC];
__device__ __nv_bfloat16 g_c_lo [(size_t)B_ * NK * DC];
__device__ __nv_bfloat16 g_q_hi [(size_t)B_ * NQ * INNER];
__device__ __nv_bfloat16 g_q_lo [(size_t)B_ * NQ * INNER];
__device__ __nv_bfloat16 g_k_hi [(size_t)B_ * NK * INNER];
__device__ __nv_bfloat16 g_k_lo [(size_t)B_ * NK * INNER];
__device__ __nv_bfloat16 g_v_hi [(size_t)B_ * NK * INNER];
__device__ __nv_bfloat16 g_v_lo [(size_t)B_ * NK * INNER];
__device__ __nv_bfloat16 g_ao_hi[(size_t)B_ * NQ * INNER];
__device__ __nv_bfloat16 g_ao_lo[(size_t)B_ * NQ * INNER];
__device__ __nv_bfloat16 g_wq_hi[(size_t)DQ * INNER];
__device__ __nv_bfloat16 g_wq_lo[(size_t)DQ * INNER];
__device__ __nv_bfloat16 g_wk_hi[(size_t)DC * INNER];
__device__ __nv_bfloat16 g_wk_lo[(size_t)DC * INNER];
__device__ __nv_bfloat16 g_wv_hi[(size_t)DC * INNER];
__device__ __nv_bfloat16 g_wv_lo[(size_t)DC * INNER];
__device__ __nv_bfloat16 g_wo_hi[(size_t)INNER * DQ];
__device__ __nv_bfloat16 g_wo_lo[(size_t)INNER * DQ];

// ---------------------------------------------------------------------------
// PTX helpers (sm_80-era only: cp.async, ldmatrix, mma.sync)
// ---------------------------------------------------------------------------
__device__ __forceinline__ uint32_t smem_u32(const void* p) {
    uint32_t a;
    asm("{ .reg .u64 t; cvta.to.shared.u64 t, %1; cvt.u32.u64 %0, t; }"
        : "=r"(a) : "l"(p));
    return a;
}
__device__ __forceinline__ void cp_async16(uint32_t s, const void* g) {
    asm volatile("cp.async.cg.shared.global [%0], [%1], 16;" :: "r"(s), "l"(g));
}
__device__ __forceinline__ void ldsm_x4(uint32_t* r, uint32_t a) {
    asm volatile("ldmatrix.sync.aligned.m8n8.x4.shared.b16 {%0,%1,%2,%3}, [%4];"
                 : "=r"(r[0]), "=r"(r[1]), "=r"(r[2]), "=r"(r[3]) : "r"(a));
}
__device__ __forceinline__ void ldsm_x4_t(uint32_t* r, uint32_t a) {
    asm volatile("ldmatrix.sync.aligned.m8n8.x4.trans.shared.b16 {%0,%1,%2,%3}, [%4];"
                 : "=r"(r[0]), "=r"(r[1]), "=r"(r[2]), "=r"(r[3]) : "r"(a));
}
__device__ __forceinline__ void mma_bf16(float* d, const uint32_t a[4],
                                         uint32_t b0, uint32_t b1) {
    asm volatile(
        "mma.sync.aligned.m16n8k16.row.col.f32.bf16.bf16.f32 "
        "{%0,%1,%2,%3}, {%4,%5,%6,%7}, {%8,%9}, {%0,%1,%2,%3};"
        : "+f"(d[0]), "+f"(d[1]), "+f"(d[2]), "+f"(d[3])
        : "r"(a[0]), "r"(a[1]), "r"(a[2]), "r"(a[3]), "r"(b0), "r"(b1));
}
#define SW64(o)  ((o) ^ (((o) >> 3) & 0x30))
#define SW128(o) ((o) ^ (((o) >> 3) & 0x70))
#define CP_COMMIT() asm volatile("cp.async.commit_group;" ::: "memory")
#define CP_WAIT0()  asm volatile("cp.async.wait_group 0;" ::: "memory")
#define CP_WAIT1()  asm volatile("cp.async.wait_group 1;" ::: "memory")

__device__ __forceinline__ uint32_t pack_bf(float a, float b) {
    __nv_bfloat162 t = __halves2bfloat162(__float2bfloat16(a), __float2bfloat16(b));
    return *(uint32_t*)&t;
}
__device__ __forceinline__ uint32_t pack_bf_lo(float a, float b, uint32_t hp) {
    __nv_bfloat162 h = *(__nv_bfloat162*)&hp;
    return pack_bf(a - __bfloat162float(h.x), b - __bfloat162float(h.y));
}
__device__ __forceinline__ void store_split(__nv_bfloat16* H, __nv_bfloat16* L,
                                            size_t idx, float a, float b) {
    uint32_t hp = pack_bf(a, b);
    uint32_t lp = pack_bf_lo(a, b, hp);
    *(uint32_t*)(H + idx) = hp;
    *(uint32_t*)(L + idx) = lp;
}

// ---------------------------------------------------------------------------
// bf16-split GEMM: C = (Ah+Al)[M,K] @ (Wh+Wl)[K,N]. W natural [K,N], B-frags
// via ldmatrix.trans. CTA 128x128x32, 512 thr (16 warps 4x4), warp tile 32x32.
// 3-stage cp.async ring. MODE 0: hi/lo bf16 out (z selects set); MODE 1: f32+bias.
// ---------------------------------------------------------------------------
#define GSTAGE_B  32768                // Ah(8K) Al(8K) Bh(8K) Bl(8K)
#define GEMM_SMEM (3 * GSTAGE_B)       // 96 KB

template <int MODE>
__global__ __launch_bounds__(512)
void mma_gemm(const __nv_bfloat16* __restrict__ Ah, const __nv_bfloat16* __restrict__ Al,
              const __nv_bfloat16* __restrict__ W0h, const __nv_bfloat16* __restrict__ W0l,
              __nv_bfloat16* __restrict__ C0h, __nv_bfloat16* __restrict__ C0l,
              const __nv_bfloat16* __restrict__ W1h, const __nv_bfloat16* __restrict__ W1l,
              __nv_bfloat16* __restrict__ C1h, __nv_bfloat16* __restrict__ C1l,
              const float* __restrict__ bias, float* __restrict__ Cf,
              int M, int N, int K)
{
    extern __shared__ __align__(1024) char smraw[];
    const uint32_t sb = smem_u32(smraw);
    const int tid  = threadIdx.x;
    const int wid  = tid >> 5, lane = tid & 31;
    const int wm   = wid & 3,  wn   = wid >> 2;     // 4 x 4 warp grid
    const int row0 = blockIdx.y * 128, col0 = blockIdx.x * 128;
    const int nch  = K >> 5;
    const int lsel = lane & 15;
    const int khf  = (lane >> 4) * 16;
    const int tt   = lane >> 3;

    const __nv_bfloat16* Wh = (blockIdx.z == 0) ? W0h : W1h;
    const __nv_bfloat16* Wl = (blockIdx.z == 0) ? W0l : W1l;
    __nv_bfloat16* Ch = (blockIdx.z == 0) ? C0h : C1h;
    __nv_bfloat16* Cl = (blockIdx.z == 0) ? C0l : C1l;

    float acc[2][4][4];
#pragma unroll
    for (int i = 0; i < 2; i++)
#pragma unroll
        for (int j = 0; j < 4; j++)
#pragma unroll
            for (int q = 0; q < 4; q++) acc[i][j][q] = 0.f;

    const __nv_bfloat16* aH = Ah + (size_t)row0 * K;
    const __nv_bfloat16* aL = Al + (size_t)row0 * K;

    // stage layout: [Ah 8K][Al 8K][Bh 8K][Bl 8K]; B tile = [half][32k][64n]
#define GISSUE(c)                                                              \
    do {                                                                       \
        const uint32_t stg_ = sb + ((c) % 3) * GSTAGE_B;                       \
        const int k0_ = (c) << 5;                                              \
        _Pragma("unroll")                                                      \
        for (int j = 0; j < 4; j++) {                                          \
            const int idx  = tid + 512 * j;                                    \
            const int tile = j;            /* 0:Ah 1:Al 2:Bh 3:Bl */           \
            const int cc   = idx & 511;                                        \
            if (tile < 2) {                                                    \
                const int r = cc >> 2, cl = cc & 3;                            \
                const uint32_t off = r * 64 + cl * 16;                         \
                const __nv_bfloat16* src = (tile ? aL : aH)                    \
                    + (size_t)r * K + k0_ + cl * 8;                            \
                cp_async16(stg_ + tile * 8192 + SW64(off), src);               \
            } else {                                                           \
                const int half = cc >> 8, r = (cc >> 3) & 31, seg = cc & 7;    \
                const uint32_t off = r * 128 + seg * 16;                       \
                const __nv_bfloat16* src = (tile == 2 ? Wh : Wl)               \
                    + (size_t)(k0_ + r) * N + col0 + half * 64 + seg * 8;      \
                cp_async16(stg_ + tile * 8192 + half * 4096 + SW128(off), src);\
            }                                                                  \
        }                                                                      \
        CP_COMMIT();                                                           \
    } while (0)

    GISSUE(0);
    GISSUE(1);
    for (int c = 0; c < nch; c++) {
        if (c + 1 < nch) { CP_WAIT1(); } else { CP_WAIT0(); }
        __syncthreads();
        if (c + 2 < nch) GISSUE(c + 2);

        const uint32_t stg = sb + (c % 3) * GSTAGE_B;
#pragma unroll
        for (int ks = 0; ks < 2; ks++) {
            uint32_t ah[2][4], al[2][4], bh[2][4], bl[2][4];
#pragma unroll
            for (int mt = 0; mt < 2; mt++) {
                const uint32_t off = (wm * 32 + mt * 16 + lsel) * 64 + ks * 32 + khf;
                ldsm_x4(ah[mt], stg + SW64(off));
                ldsm_x4(al[mt], stg + 8192 + SW64(off));
            }
#pragma unroll
            for (int gg = 0; gg < 2; gg++) {
                const int g = (wn & 1) * 2 + gg;
                const uint32_t off = (ks * 16 + (lane & 7) + ((tt >> 1) << 3)) * 128
                                     + g * 32 + (tt & 1) * 16;
                const uint32_t sw = SW128(off) + (wn >> 1) * 4096;
                ldsm_x4_t(bh[gg], stg + 16384 + sw);
                ldsm_x4_t(bl[gg], stg + 24576 + sw);
            }
            // term-major ordering (acc reuse distance 8)
#pragma unroll
            for (int gg = 0; gg < 2; gg++)
#pragma unroll
                for (int mt = 0; mt < 2; mt++)
#pragma unroll
                    for (int nt = 0; nt < 2; nt++)
                        mma_bf16(acc[mt][gg * 2 + nt], ah[mt], bh[gg][nt], bh[gg][2 + nt]);
#pragma unroll
            for (int gg = 0; gg < 2; gg++)
#pragma unroll
                for (int mt = 0; mt < 2; mt++)
#pragma unroll
                    for (int nt = 0; nt < 2; nt++)
                        mma_bf16(acc[mt][gg * 2 + nt], ah[mt], bl[gg][nt], bl[gg][2 + nt]);
#pragma unroll
            for (int gg = 0; gg < 2; gg++)
#pragma unroll
                for (int mt = 0; mt < 2; mt++)
#pragma unroll
                    for (int nt = 0; nt < 2; nt++)
                        mma_bf16(acc[mt][gg * 2 + nt], al[mt], bh[gg][nt], bh[gg][2 + nt]);
        }
    }
#undef GISSUE

    // Epilogue
    const int rb = row0 + wm * 32 + (lane >> 2);
    const int cb = col0 + wn * 32 + (lane & 3) * 2;
#pragma unroll
    for (int mt = 0; mt < 2; mt++) {
#pragma unroll
        for (int j = 0; j < 4; j++) {
            const int col = cb + j * 8;
            const int r0 = rb + mt * 16;
            float d0 = acc[mt][j][0], d1 = acc[mt][j][1];
            float d2 = acc[mt][j][2], d3 = acc[mt][j][3];
            if (MODE == 1) {
                float b0 = bias[col], b1 = bias[col + 1];
                *(float2*)(Cf + (size_t)r0 * N + col)       = make_float2(d0 + b0, d1 + b1);
                *(float2*)(Cf + (size_t)(r0 + 8) * N + col) = make_float2(d2 + b0, d3 + b1);
            } else {
                store_split(Ch, Cl, (size_t)r0 * N + col, d0, d1);
                store_split(Ch, Cl, (size_t)(r0 + 8) * N + col, d2, d3);
            }
        }
    }
}

// ---------------------------------------------------------------------------
// Flash attention via mma.sync, bf16 3-term split (unchanged from round 5)
// ---------------------------------------------------------------------------
#define AQ_H 0
#define AQ_L 16384
#define AR_BASE  32768
#define AR_STAGE 32768
#define AK_H 0
#define AK_L 8192
#define AV_H 16384
#define AV_L 24576
#define ATTN_SMEM (32768 + 3 * 32768)   // 128 KB

__global__ __launch_bounds__(256)
void attn_mma(const __nv_bfloat16* __restrict__ qh, const __nv_bfloat16* __restrict__ ql,
              const __nv_bfloat16* __restrict__ kh, const __nv_bfloat16* __restrict__ kl,
              const __nv_bfloat16* __restrict__ vh, const __nv_bfloat16* __restrict__ vl,
              __nv_bfloat16* __restrict__ aoh, __nv_bfloat16* __restrict__ aol)
{
    extern __shared__ __align__(1024) char smraw[];
    const uint32_t sb = smem_u32(smraw);
    const int tid = threadIdx.x, lane = tid & 31, w = tid >> 5;
    const int q0 = blockIdx.x * 128;
    const int h  = blockIdx.y;
    const int b  = blockIdx.z;
    const int lsel = lane & 15;
    const int khf  = (lane >> 4) * 16;
    const float SCALE = 0.125f;

    const size_t qgb = ((size_t)b * NQ + q0) * INNER + h * DH;
#pragma unroll
    for (int j = 0; j < 8; j++) {
        int idx = tid + 256 * j;
        int bq  = idx >> 10;
        int cc  = idx & 1023;
        int r = cc >> 3, seg = cc & 7;
        uint32_t off = r * 128 + seg * 16;
        const __nv_bfloat16* src = (bq ? ql : qh) + qgb + (size_t)r * INNER + seg * 8;
        *(float4*)(smraw + (bq ? AQ_L : AQ_H) + SW128(off)) = *(const float4*)src;
    }
    __syncthreads();

    uint32_t qfh[4][4], qfl[4][4];
#pragma unroll
    for (int ks = 0; ks < 4; ks++) {
        uint32_t off = (w * 16 + lsel) * 128 + ks * 32 + khf;
        ldsm_x4(qfh[ks], sb + AQ_H + SW128(off));
        ldsm_x4(qfl[ks], sb + AQ_L + SW128(off));
    }

    float oacc[8][4];
#pragma unroll
    for (int j = 0; j < 8; j++)
#pragma unroll
        for (int q = 0; q < 4; q++) oacc[j][q] = 0.f;
    float m0 = -1e30f, m1 = -1e30f, l0 = 0.f, l1 = 0.f;

#define AT_ISSUE(kt)                                                           \
    do {                                                                       \
        const uint32_t stg_ = sb + AR_BASE + ((kt) % 3) * AR_STAGE;            \
        const size_t kvg = ((size_t)b * NK + (kt) * 64) * INNER + h * DH;      \
        _Pragma("unroll")                                                      \
        for (int j = 0; j < 8; j++) {                                          \
            int idx = tid + 256 * j;                                           \
            int buf = idx >> 9;                                                \
            int cc  = idx & 511;                                               \
            int r = cc >> 3, seg = cc & 7;                                     \
            uint32_t off = r * 128 + seg * 16;                                 \
            const __nv_bfloat16* src =                                         \
                (buf == 0 ? kh : buf == 1 ? kl : buf == 2 ? vh : vl)           \
                + kvg + (size_t)r * INNER + seg * 8;                           \
            cp_async16(stg_ + buf * 8192 + SW128(off), src);                   \
        }                                                                      \
        CP_COMMIT();                                                           \
    } while (0)

    const int NT = NK / 64;
    AT_ISSUE(0);
    AT_ISSUE(1);
    for (int kt = 0; kt < NT; kt++) {
        if (kt + 1 < NT) { CP_WAIT1(); } else { CP_WAIT0(); }
        __syncthreads();
        if (kt + 2 < NT) AT_ISSUE(kt + 2);
        const uint32_t stg = sb + AR_BASE + (kt % 3) * AR_STAGE;

        float sacc[8][4];
#pragma unroll
        for (int j = 0; j < 8; j++)
#pragma unroll
            for (int q = 0; q < 4; q++) sacc[j][q] = 0.f;

#pragma unroll
        for (int ks = 0; ks < 4; ks++) {
            uint32_t bh[4][4], bl[4][4];
#pragma unroll
            for (int g = 0; g < 4; g++) {
                uint32_t off = (g * 16 + lsel) * 128 + ks * 32 + khf;
                ldsm_x4(bh[g], stg + AK_H + SW128(off));
                ldsm_x4(bl[g], stg + AK_L + SW128(off));
            }
#pragma unroll
            for (int g = 0; g < 4; g++)
#pragma unroll
                for (int nt = 0; nt < 2; nt++)
                    mma_bf16(sacc[g * 2 + nt], qfh[ks], bh[g][nt], bh[g][2 + nt]);
#pragma unroll
            for (int g = 0; g < 4; g++)
#pragma unroll
                for (int nt = 0; nt < 2; nt++)
                    mma_bf16(sacc[g * 2 + nt], qfh[ks], bl[g][nt], bl[g][2 + nt]);
#pragma unroll
            for (int g = 0; g < 4; g++)
#pragma unroll
                for (int nt = 0; nt < 2; nt++)
                    mma_bf16(sacc[g * 2 + nt], qfl[ks], bh[g][nt], bh[g][2 + nt]);
        }

        float rx0 = -1e30f, rx1 = -1e30f;
#pragma unroll
        for (int j = 0; j < 8; j++) {
            rx0 = fmaxf(rx0, fmaxf(sacc[j][0], sacc[j][1]));
            rx1 = fmaxf(rx1, fmaxf(sacc[j][2], sacc[j][3]));
        }
#pragma unroll
        for (int off = 1; off <= 2; off <<= 1) {
            rx0 = fmaxf(rx0, __shfl_xor_sync(0xffffffffu, rx0, off));
            rx1 = fmaxf(rx1, __shfl_xor_sync(0xffffffffu, rx1, off));
        }
        float nm0 = fmaxf(m0, rx0 * SCALE), nm1 = fmaxf(m1, rx1 * SCALE);
        float c0 = __expf(m0 - nm0), c1 = __expf(m1 - nm1);
        m0 = nm0; m1 = nm1;

        float ps0 = 0.f, ps1 = 0.f;
        uint32_t pah[4][4], pal[4][4];
#pragma unroll
        for (int t = 0; t < 4; t++) {
#pragma unroll
            for (int jj = 0; jj < 2; jj++) {
                int j = 2 * t + jj;
                float p00 = __expf(fmaf(sacc[j][0], SCALE, -nm0));
                float p01 = __expf(fmaf(sacc[j][1], SCALE, -nm0));
                float p10 = __expf(fmaf(sacc[j][2], SCALE, -nm1));
                float p11 = __expf(fmaf(sacc[j][3], SCALE, -nm1));
                ps0 += p00 + p01;
                ps1 += p10 + p11;
                uint32_t h0 = pack_bf(p00, p01), h1 = pack_bf(p10, p11);
                pah[t][jj * 2]     = h0;
                pah[t][jj * 2 + 1] = h1;
                pal[t][jj * 2]     = pack_bf_lo(p00, p01, h0);
                pal[t][jj * 2 + 1] = pack_bf_lo(p10, p11, h1);
            }
        }
#pragma unroll
        for (int off = 1; off <= 2; off <<= 1) {
            ps0 += __shfl_xor_sync(0xffffffffu, ps0, off);
            ps1 += __shfl_xor_sync(0xffffffffu, ps1, off);
        }
        l0 = l0 * c0 + ps0;
        l1 = l1 * c1 + ps1;
#pragma unroll
        for (int j = 0; j < 8; j++) {
            oacc[j][0] *= c0; oacc[j][1] *= c0;
            oacc[j][2] *= c1; oacc[j][3] *= c1;
        }

        const int tt = lane >> 3;
#pragma unroll
        for (int t = 0; t < 4; t++) {
            uint32_t vbh[4][4], vbl[4][4];
#pragma unroll
            for (int g = 0; g < 4; g++) {
                uint32_t off = (t * 16 + (lane & 7) + (tt >> 1) * 8) * 128
                               + g * 32 + (tt & 1) * 16;
                ldsm_x4_t(vbh[g], stg + AV_H + SW128(off));
                ldsm_x4_t(vbl[g], stg + AV_L + SW128(off));
            }
#pragma unroll
            for (int g = 0; g < 4; g++)
#pragma unroll
                for (int nt = 0; nt < 2; nt++)
                    mma_bf16(oacc[g * 2 + nt], pah[t], vbh[g][nt], vbh[g][2 + nt]);
#pragma unroll
            for (int g = 0; g < 4; g++)
#pragma unroll
                for (int nt = 0; nt < 2; nt++)
                    mma_bf16(oacc[g * 2 + nt], pah[t], vbl[g][nt], vbl[g][2 + nt]);
#pragma unroll
            for (int g = 0; g < 4; g++)
#pragma unroll
                for (int nt = 0; nt < 2; nt++)
                    mma_bf16(oacc[g * 2 + nt], pal[t], vbh[g][nt], vbh[g][2 + nt]);
        }
    }
#undef AT_ISSUE

    const float inv0 = 1.f / l0, inv1 = 1.f / l1;
    const int r0g = q0 + w * 16 + (lane >> 2);
    const int r1g = r0g + 8;
    const int cbase = h * DH + (lane & 3) * 2;
#pragma unroll
    for (int j = 0; j < 8; j++) {
        const int col = cbase + j * 8;
        store_split(aoh, aol, ((size_t)b * NQ + r0g) * INNER + col,
                    oacc[j][0] * inv0, oacc[j][1] * inv0);
        store_split(aoh, aol, ((size_t)b * NQ + r1g) * INNER + col,
                    oacc[j][2] * inv1, oacc[j][3] * inv1);
    }
}

// ---------------------------------------------------------------------------
// One fused fp32 -> bf16 hi/lo split over x, ctx, and all 4 weights (natural)
// ---------------------------------------------------------------------------
#define N4_X  (B_ * NQ * DQ / 4)
#define N4_C  (B_ * NK * DC / 4)
#define N4_WQ (DQ * INNER / 4)
#define N4_WK (DC * INNER / 4)
#define N4_WV (DC * INNER / 4)
#define N4_WO (INNER * DQ / 4)
#define C1_ (N4_X)
#define C2_ (C1_ + N4_C)
#define C3_ (C2_ + N4_WQ)
#define C4_ (C3_ + N4_WK)
#define C5_ (C4_ + N4_WV)
#define C6_ (C5_ + N4_WO)

__global__ void split_all(const float4* __restrict__ x, const float4* __restrict__ ctx,
                          const float4* __restrict__ wq, const float4* __restrict__ wk,
                          const float4* __restrict__ wv, const float4* __restrict__ wo)
{
    int i = blockIdx.x * blockDim.x + threadIdx.x;
    if (i >= C6_) return;
    const float4* in;
    __nv_bfloat162 *hi, *lo;
    int idx;
    if      (i < C1_) { in = x;   hi = (__nv_bfloat162*)g_x_hi; lo = (__nv_bfloat162*)g_x_lo; idx = i; }
    else if (i < C2_) { in = ctx; hi = (__nv_bfloat162*)g_c_hi; lo = (__nv_bfloat162*)g_c_lo; idx = i - C1_; }
    else if (i < C3_) { in = wq;  hi = (__nv_bfloat162*)g_wq_hi; lo = (__nv_bfloat162*)g_wq_lo; idx = i - C2_; }
    else if (i < C4_) { in = wk;  hi = (__nv_bfloat162*)g_wk_hi; lo = (__nv_bfloat162*)g_wk_lo; idx = i - C3_; }
    else if (i < C5_) { in = wv;  hi = (__nv_bfloat162*)g_wv_hi; lo = (__nv_bfloat162*)g_wv_lo; idx = i - C4_; }
    else              { in = wo;  hi = (__nv_bfloat162*)g_wo_hi; lo = (__nv_bfloat162*)g_wo_lo; idx = i - C5_; }
    float4 v = in[idx];
    __nv_bfloat16 h0 = __float2bfloat16(v.x), h1 = __float2bfloat16(v.y);
    __nv_bfloat16 h2 = __float2bfloat16(v.z), h3 = __float2bfloat16(v.w);
    hi[2 * idx]     = __halves2bfloat162(h0, h1);
    hi[2 * idx + 1] = __halves2bfloat162(h2, h3);
    lo[2 * idx]     = __halves2bfloat162(
        __float2bfloat16(v.x - __bfloat162float(h0)),
        __float2bfloat16(v.y - __bfloat162float(h1)));
    lo[2 * idx + 1] = __halves2bfloat162(
        __float2bfloat16(v.z - __bfloat162float(h2)),
        __float2bfloat16(v.w - __bfloat162float(h3)));
}

// ---------------------------------------------------------------------------
// Launch: split(0), gemmQ(1), gemmKV(2), attn(3) <- ncu slot, gemmO(4)
// ---------------------------------------------------------------------------
extern "C" void kernel_launch(void* const* d_in, const int* in_sizes, int n_in,
                              void* d_out, int out_size)
{
    const float* x   = (const float*)d_in[0];
    const float* ctx = (const float*)d_in[1];
    const float* Wq  = (const float*)d_in[2];
    const float* Wk  = (const float*)d_in[3];
    const float* Wv  = (const float*)d_in[4];
    const float* Wo  = (const float*)d_in[5];
    const float* bo  = (const float*)d_in[6];
    float* out = (float*)d_out;

    __nv_bfloat16 *xh, *xl, *ch, *cl;
    __nv_bfloat16 *qhp, *qlp, *khp, *klp, *vhp, *vlp, *aoh, *aol;
    __nv_bfloat16 *wqh, *wql, *wkh, *wkl, *wvh, *wvl, *woh, *wol;
    cudaGetSymbolAddress((void**)&xh,  g_x_hi);  cudaGetSymbolAddress((void**)&xl,  g_x_lo);
    cudaGetSymbolAddress((void**)&ch,  g_c_hi);  cudaGetSymbolAddress((void**)&cl,  g_c_lo);
    cudaGetSymbolAddress((void**)&qhp, g_q_hi);  cudaGetSymbolAddress((void**)&qlp, g_q_lo);
    cudaGetSymbolAddress((void**)&khp, g_k_hi);  cudaGetSymbolAddress((void**)&klp, g_k_lo);
    cudaGetSymbolAddress((void**)&vhp, g_v_hi);  cudaGetSymbolAddress((void**)&vlp, g_v_lo);
    cudaGetSymbolAddress((void**)&aoh, g_ao_hi); cudaGetSymbolAddress((void**)&aol, g_ao_lo);
    cudaGetSymbolAddress((void**)&wqh, g_wq_hi); cudaGetSymbolAddress((void**)&wql, g_wq_lo);
    cudaGetSymbolAddress((void**)&wkh, g_wk_hi); cudaGetSymbolAddress((void**)&wkl, g_wk_lo);
    cudaGetSymbolAddress((void**)&wvh, g_wv_hi); cudaGetSymbolAddress((void**)&wvl, g_wv_lo);
    cudaGetSymbolAddress((void**)&woh, g_wo_hi); cudaGetSymbolAddress((void**)&wol, g_wo_lo);

    cudaFuncSetAttribute(mma_gemm<0>, cudaFuncAttributeMaxDynamicSharedMemorySize, GEMM_SMEM);
    cudaFuncSetAttribute(mma_gemm<1>, cudaFuncAttributeMaxDynamicSharedMemorySize, GEMM_SMEM);
    cudaFuncSetAttribute(attn_mma, cudaFuncAttributeMaxDynamicSharedMemorySize, ATTN_SMEM);

    // 0: all splits (activations + weights, natural layout)
    split_all<<<(C6_ + 255) / 256, 256>>>(
        (const float4*)x, (const float4*)ctx, (const float4*)Wq,
        (const float4*)Wk, (const float4*)Wv, (const float4*)Wo);

    // 1: Q projection
    mma_gemm<0><<<dim3(INNER / 128, (B_ * NQ) / 128, 1), 512, GEMM_SMEM>>>(
        xh, xl, wqh, wql, qhp, qlp, wqh, wql, qhp, qlp,
        nullptr, nullptr, B_ * NQ, INNER, DQ);

    // 2: fused K+V projections (z selects)
    mma_gemm<0><<<dim3(INNER / 128, (B_ * NK) / 128, 2), 512, GEMM_SMEM>>>(
        ch, cl, wkh, wkl, khp, klp, wvh, wvl, vhp, vlp,
        nullptr, nullptr, B_ * NK, INNER, DC);

    // 3: attention  (ncu capture slot)
    attn_mma<<<dim3(NQ / 128, HEADS, B_), 256, ATTN_SMEM>>>(
        qhp, qlp, khp, klp, vhp, vlp, aoh, aol);

    // 4: output projection -> fp32 + bias
    mma_gemm<1><<<dim3(DQ / 128, (B_ * NQ) / 128, 1), 512, GEMM_SMEM>>>(
        aoh, aol, woh, wol, nullptr, nullptr, woh, wol, nullptr, nullptr,
        bo, out, B_ * NQ, DQ, INNER);
}

// round 7
// speedup vs baseline: 2.7571x; 1.0934x over previous
#include <cuda_runtime.h>
#include <cuda_bf16.h>
#include <cstdint>

// Problem constants
#define B_     4
#define NQ     2048
#define DQ     1024
#define NK     1024
#define DC     768
#define HEADS  16
#define DH     64
#define INNER  1024   // HEADS*DH

// ---------------------------------------------------------------------------
// Device scratch (static globals). All bf16 hi/lo. Weights kept NATURAL [K,N].
// ---------------------------------------------------------------------------
__device__ __nv_bfloat16 g_x_hi [(size_t)B_ * NQ * DQ];
__device__ __nv_bfloat16 g_x_lo [(size_t)B_ * NQ * DQ];
__device__ __nv_bfloat16 g_c_hi [(size_t)B_ * NK * DC];
__device__ __nv_bfloat16 g_c_lo [(size_t)B_ * NK * DC];
__device__ __nv_bfloat16 g_q_hi [(size_t)B_ * NQ * INNER];
__device__ __nv_bfloat16 g_q_lo [(size_t)B_ * NQ * INNER];
__device__ __nv_bfloat16 g_k_hi [(size_t)B_ * NK * INNER];
__device__ __nv_bfloat16 g_k_lo [(size_t)B_ * NK * INNER];
__device__ __nv_bfloat16 g_v_hi [(size_t)B_ * NK * INNER];
__device__ __nv_bfloat16 g_v_lo [(size_t)B_ * NK * INNER];
__device__ __nv_bfloat16 g_ao_hi[(size_t)B_ * NQ * INNER];
__device__ __nv_bfloat16 g_ao_lo[(size_t)B_ * NQ * INNER];
__device__ __nv_bfloat16 g_wq_hi[(size_t)DQ * INNER];
__device__ __nv_bfloat16 g_wq_lo[(size_t)DQ * INNER];
__device__ __nv_bfloat16 g_wk_hi[(size_t)DC * INNER];
__device__ __nv_bfloat16 g_wk_lo[(size_t)DC * INNER];
__device__ __nv_bfloat16 g_wv_hi[(size_t)DC * INNER];
__device__ __nv_bfloat16 g_wv_lo[(size_t)DC * INNER];
__device__ __nv_bfloat16 g_wo_hi[(size_t)INNER * DQ];
__device__ __nv_bfloat16 g_wo_lo[(size_t)INNER * DQ];

// ---------------------------------------------------------------------------
// PTX helpers (sm_80-era only: cp.async, ldmatrix, mma.sync)
// ---------------------------------------------------------------------------
__device__ __forceinline__ uint32_t smem_u32(const void* p) {
    uint32_t a;
    asm("{ .reg .u64 t; cvta.to.shared.u64 t, %1; cvt.u32.u64 %0, t; }"
        : "=r"(a) : "l"(p));
    return a;
}
__device__ __forceinline__ void cp_async16(uint32_t s, const void* g) {
    asm volatile("cp.async.cg.shared.global [%0], [%1], 16;" :: "r"(s), "l"(g));
}
__device__ __forceinline__ void ldsm_x4(uint32_t* r, uint32_t a) {
    asm volatile("ldmatrix.sync.aligned.m8n8.x4.shared.b16 {%0,%1,%2,%3}, [%4];"
                 : "=r"(r[0]), "=r"(r[1]), "=r"(r[2]), "=r"(r[3]) : "r"(a));
}
__device__ __forceinline__ void ldsm_x4_t(uint32_t* r, uint32_t a) {
    asm volatile("ldmatrix.sync.aligned.m8n8.x4.trans.shared.b16 {%0,%1,%2,%3}, [%4];"
                 : "=r"(r[0]), "=r"(r[1]), "=r"(r[2]), "=r"(r[3]) : "r"(a));
}
__device__ __forceinline__ void mma_bf16(float* d, const uint32_t a[4],
                                         uint32_t b0, uint32_t b1) {
    asm volatile(
        "mma.sync.aligned.m16n8k16.row.col.f32.bf16.bf16.f32 "
        "{%0,%1,%2,%3}, {%4,%5,%6,%7}, {%8,%9}, {%0,%1,%2,%3};"
        : "+f"(d[0]), "+f"(d[1]), "+f"(d[2]), "+f"(d[3])
        : "r"(a[0]), "r"(a[1]), "r"(a[2]), "r"(a[3]), "r"(b0), "r"(b1));
}
#define SW64(o)  ((o) ^ (((o) >> 3) & 0x30))
#define SW128(o) ((o) ^ (((o) >> 3) & 0x70))
#define CP_COMMIT() asm volatile("cp.async.commit_group;" ::: "memory")
#define CP_WAIT0()  asm volatile("cp.async.wait_group 0;" ::: "memory")
#define CP_WAIT1()  asm volatile("cp.async.wait_group 1;" ::: "memory")

__device__ __forceinline__ uint32_t pack_bf(float a, float b) {
    __nv_bfloat162 t = __halves2bfloat162(__float2bfloat16(a), __float2bfloat16(b));
    return *(uint32_t*)&t;
}
__device__ __forceinline__ uint32_t pack_bf_lo(float a, float b, uint32_t hp) {
    __nv_bfloat162 h = *(__nv_bfloat162*)&hp;
    return pack_bf(a - __bfloat162float(h.x), b - __bfloat162float(h.y));
}
__device__ __forceinline__ void store_split(__nv_bfloat16* H, __nv_bfloat16* L,
                                            size_t idx, float a, float b) {
    uint32_t hp = pack_bf(a, b);
    uint32_t lp = pack_bf_lo(a, b, hp);
    *(uint32_t*)(H + idx) = hp;
    *(uint32_t*)(L + idx) = lp;
}

// ---------------------------------------------------------------------------
// bf16-split GEMM (unchanged from round 6): C = (Ah+Al)[M,K] @ (Wh+Wl)[K,N].
// CTA 128x128x32, 512 thr (16 warps 4x4), warp tile 32x32, 3-stage ring.
// ---------------------------------------------------------------------------
#define GSTAGE_B  32768                // Ah(8K) Al(8K) Bh(8K) Bl(8K)
#define GEMM_SMEM (3 * GSTAGE_B)       // 96 KB

template <int MODE>
__global__ __launch_bounds__(512)
void mma_gemm(const __nv_bfloat16* __restrict__ Ah, const __nv_bfloat16* __restrict__ Al,
              const __nv_bfloat16* __restrict__ W0h, const __nv_bfloat16* __restrict__ W0l,
              __nv_bfloat16* __restrict__ C0h, __nv_bfloat16* __restrict__ C0l,
              const __nv_bfloat16* __restrict__ W1h, const __nv_bfloat16* __restrict__ W1l,
              __nv_bfloat16* __restrict__ C1h, __nv_bfloat16* __restrict__ C1l,
              const float* __restrict__ bias, float* __restrict__ Cf,
              int M, int N, int K)
{
    extern __shared__ __align__(1024) char smraw[];
    const uint32_t sb = smem_u32(smraw);
    const int tid  = threadIdx.x;
    const int wid  = tid >> 5, lane = tid & 31;
    const int wm   = wid & 3,  wn   = wid >> 2;     // 4 x 4 warp grid
    const int row0 = blockIdx.y * 128, col0 = blockIdx.x * 128;
    const int nch  = K >> 5;
    const int lsel = lane & 15;
    const int khf  = (lane >> 4) * 16;
    const int tt   = lane >> 3;

    const __nv_bfloat16* Wh = (blockIdx.z == 0) ? W0h : W1h;
    const __nv_bfloat16* Wl = (blockIdx.z == 0) ? W0l : W1l;
    __nv_bfloat16* Ch = (blockIdx.z == 0) ? C0h : C1h;
    __nv_bfloat16* Cl = (blockIdx.z == 0) ? C0l : C1l;

    float acc[2][4][4];
#pragma unroll
    for (int i = 0; i < 2; i++)
#pragma unroll
        for (int j = 0; j < 4; j++)
#pragma unroll
            for (int q = 0; q < 4; q++) acc[i][j][q] = 0.f;

    const __nv_bfloat16* aH = Ah + (size_t)row0 * K;
    const __nv_bfloat16* aL = Al + (size_t)row0 * K;

#define GISSUE(c)                                                              \
    do {                                                                       \
        const uint32_t stg_ = sb + ((c) % 3) * GSTAGE_B;                       \
        const int k0_ = (c) << 5;                                              \
        _Pragma("unroll")                                                      \
        for (int j = 0; j < 4; j++) {                                          \
            const int idx  = tid + 512 * j;                                    \
            const int tile = j;            /* 0:Ah 1:Al 2:Bh 3:Bl */           \
            const int cc   = idx & 511;                                        \
            if (tile < 2) {                                                    \
                const int r = cc >> 2, cl = cc & 3;                            \
                const uint32_t off = r * 64 + cl * 16;                         \
                const __nv_bfloat16* src = (tile ? aL : aH)                    \
                    + (size_t)r * K + k0_ + cl * 8;                            \
                cp_async16(stg_ + tile * 8192 + SW64(off), src);               \
            } else {                                                           \
                const int half = cc >> 8, r = (cc >> 3) & 31, seg = cc & 7;    \
                const uint32_t off = r * 128 + seg * 16;                       \
                const __nv_bfloat16* src = (tile == 2 ? Wh : Wl)               \
                    + (size_t)(k0_ + r) * N + col0 + half * 64 + seg * 8;      \
                cp_async16(stg_ + tile * 8192 + half * 4096 + SW128(off), src);\
            }                                                                  \
        }                                                                      \
        CP_COMMIT();                                                           \
    } while (0)

    GISSUE(0);
    GISSUE(1);
    for (int c = 0; c < nch; c++) {
        if (c + 1 < nch) { CP_WAIT1(); } else { CP_WAIT0(); }
        __syncthreads();
        if (c + 2 < nch) GISSUE(c + 2);

        const uint32_t stg = sb + (c % 3) * GSTAGE_B;
#pragma unroll
        for (int ks = 0; ks < 2; ks++) {
            uint32_t ah[2][4], al[2][4], bh[2][4], bl[2][4];
#pragma unroll
            for (int mt = 0; mt < 2; mt++) {
                const uint32_t off = (wm * 32 + mt * 16 + lsel) * 64 + ks * 32 + khf;
                ldsm_x4(ah[mt], stg + SW64(off));
                ldsm_x4(al[mt], stg + 8192 + SW64(off));
            }
#pragma unroll
            for (int gg = 0; gg < 2; gg++) {
                const int g = (wn & 1) * 2 + gg;
                const uint32_t off = (ks * 16 + (lane & 7) + ((tt >> 1) << 3)) * 128
                                     + g * 32 + (tt & 1) * 16;
                const uint32_t sw = SW128(off) + (wn >> 1) * 4096;
                ldsm_x4_t(bh[gg], stg + 16384 + sw);
                ldsm_x4_t(bl[gg], stg + 24576 + sw);
            }
#pragma unroll
            for (int gg = 0; gg < 2; gg++)
#pragma unroll
                for (int mt = 0; mt < 2; mt++)
#pragma unroll
                    for (int nt = 0; nt < 2; nt++)
                        mma_bf16(acc[mt][gg * 2 + nt], ah[mt], bh[gg][nt], bh[gg][2 + nt]);
#pragma unroll
            for (int gg = 0; gg < 2; gg++)
#pragma unroll
                for (int mt = 0; mt < 2; mt++)
#pragma unroll
                    for (int nt = 0; nt < 2; nt++)
                        mma_bf16(acc[mt][gg * 2 + nt], ah[mt], bl[gg][nt], bl[gg][2 + nt]);
#pragma unroll
            for (int gg = 0; gg < 2; gg++)
#pragma unroll
                for (int mt = 0; mt < 2; mt++)
#pragma unroll
                    for (int nt = 0; nt < 2; nt++)
                        mma_bf16(acc[mt][gg * 2 + nt], al[mt], bh[gg][nt], bh[gg][2 + nt]);
        }
    }
#undef GISSUE

    const int rb = row0 + wm * 32 + (lane >> 2);
    const int cb = col0 + wn * 32 + (lane & 3) * 2;
#pragma unroll
    for (int mt = 0; mt < 2; mt++) {
#pragma unroll
        for (int j = 0; j < 4; j++) {
            const int col = cb + j * 8;
            const int r0 = rb + mt * 16;
            float d0 = acc[mt][j][0], d1 = acc[mt][j][1];
            float d2 = acc[mt][j][2], d3 = acc[mt][j][3];
            if (MODE == 1) {
                float b0 = bias[col], b1 = bias[col + 1];
                *(float2*)(Cf + (size_t)r0 * N + col)       = make_float2(d0 + b0, d1 + b1);
                *(float2*)(Cf + (size_t)(r0 + 8) * N + col) = make_float2(d2 + b0, d3 + b1);
            } else {
                store_split(Ch, Cl, (size_t)r0 * N + col, d0, d1);
                store_split(Ch, Cl, (size_t)(r0 + 8) * N + col, d2, d3);
            }
        }
    }
}

// ---------------------------------------------------------------------------
// Flash attention via mma.sync, bf16 3-term split.
// NOW: 2-stage KV ring (96 KB total), launch_bounds(256,2) -> 2 CTAs/SM,
// Q fragments reloaded from smem per k-step (frees ~56 regs).
// ---------------------------------------------------------------------------
#define AQ_H 0
#define AQ_L 16384
#define AR_BASE  32768
#define AR_STAGE 32768
#define AK_H 0
#define AK_L 8192
#define AV_H 16384
#define AV_L 24576
#define ATTN_SMEM (32768 + 2 * 32768)   // 96 KB

__global__ __launch_bounds__(256, 2)
void attn_mma(const __nv_bfloat16* __restrict__ qh, const __nv_bfloat16* __restrict__ ql,
              const __nv_bfloat16* __restrict__ kh, const __nv_bfloat16* __restrict__ kl,
              const __nv_bfloat16* __restrict__ vh, const __nv_bfloat16* __restrict__ vl,
              __nv_bfloat16* __restrict__ aoh, __nv_bfloat16* __restrict__ aol)
{
    extern __shared__ __align__(1024) char smraw[];
    const uint32_t sb = smem_u32(smraw);
    const int tid = threadIdx.x, lane = tid & 31, w = tid >> 5;
    const int q0 = blockIdx.x * 128;
    const int h  = blockIdx.y;
    const int b  = blockIdx.z;
    const int lsel = lane & 15;
    const int khf  = (lane >> 4) * 16;
    const float SCALE = 0.125f;

    // Load Q tile (hi/lo) into smem, SW128
    const size_t qgb = ((size_t)b * NQ + q0) * INNER + h * DH;
#pragma unroll
    for (int j = 0; j < 8; j++) {
        int idx = tid + 256 * j;
        int bq  = idx >> 10;
        int cc  = idx & 1023;
        int r = cc >> 3, seg = cc & 7;
        uint32_t off = r * 128 + seg * 16;
        const __nv_bfloat16* src = (bq ? ql : qh) + qgb + (size_t)r * INNER + seg * 8;
        *(float4*)(smraw + (bq ? AQ_L : AQ_H) + SW128(off)) = *(const float4*)src;
    }

    float oacc[8][4];
#pragma unroll
    for (int j = 0; j < 8; j++)
#pragma unroll
        for (int q = 0; q < 4; q++) oacc[j][q] = 0.f;
    float m0 = -1e30f, m1 = -1e30f, l0 = 0.f, l1 = 0.f;

#define AT_ISSUE(kt)                                                           \
    do {                                                                       \
        const uint32_t stg_ = sb + AR_BASE + ((kt) & 1) * AR_STAGE;            \
        const size_t kvg = ((size_t)b * NK + (kt) * 64) * INNER + h * DH;      \
        _Pragma("unroll")                                                      \
        for (int j = 0; j < 8; j++) {                                          \
            int idx = tid + 256 * j;                                           \
            int buf = idx >> 9;                                                \
            int cc  = idx & 511;                                               \
            int r = cc >> 3, seg = cc & 7;                                     \
            uint32_t off = r * 128 + seg * 16;                                 \
            const __nv_bfloat16* src =                                         \
                (buf == 0 ? kh : buf == 1 ? kl : buf == 2 ? vh : vl)           \
                + kvg + (size_t)r * INNER + seg * 8;                           \
            cp_async16(stg_ + buf * 8192 + SW128(off), src);                   \
        }                                                                      \
        CP_COMMIT();                                                           \
    } while (0)

    const int NT = NK / 64;
    AT_ISSUE(0);
    for (int kt = 0; kt < NT; kt++) {
        CP_WAIT0();
        __syncthreads();                 // tile kt visible; prev compute done
        if (kt + 1 < NT) AT_ISSUE(kt + 1);
        const uint32_t stg = sb + AR_BASE + (kt & 1) * AR_STAGE;

        // ---- S = Q @ K^T : 16 rows x 64 keys per warp ----
        float sacc[8][4];
#pragma unroll
        for (int j = 0; j < 8; j++)
#pragma unroll
            for (int q = 0; q < 4; q++) sacc[j][q] = 0.f;

#pragma unroll
        for (int ks = 0; ks < 4; ks++) {
            uint32_t qfh[4], qfl[4];
            {
                uint32_t off = (w * 16 + lsel) * 128 + ks * 32 + khf;
                ldsm_x4(qfh, sb + AQ_H + SW128(off));
                ldsm_x4(qfl, sb + AQ_L + SW128(off));
            }
            uint32_t bh[4][4], bl[4][4];
#pragma unroll
            for (int g = 0; g < 4; g++) {
                uint32_t off = (g * 16 + lsel) * 128 + ks * 32 + khf;
                ldsm_x4(bh[g], stg + AK_H + SW128(off));
                ldsm_x4(bl[g], stg + AK_L + SW128(off));
            }
#pragma unroll
            for (int g = 0; g < 4; g++)
#pragma unroll
                for (int nt = 0; nt < 2; nt++)
                    mma_bf16(sacc[g * 2 + nt], qfh, bh[g][nt], bh[g][2 + nt]);
#pragma unroll
            for (int g = 0; g < 4; g++)
#pragma unroll
                for (int nt = 0; nt < 2; nt++)
                    mma_bf16(sacc[g * 2 + nt], qfh, bl[g][nt], bl[g][2 + nt]);
#pragma unroll
            for (int g = 0; g < 4; g++)
#pragma unroll
                for (int nt = 0; nt < 2; nt++)
                    mma_bf16(sacc[g * 2 + nt], qfl, bh[g][nt], bh[g][2 + nt]);
        }

        // ---- online softmax ----
        float rx0 = -1e30f, rx1 = -1e30f;
#pragma unroll
        for (int j = 0; j < 8; j++) {
            rx0 = fmaxf(rx0, fmaxf(sacc[j][0], sacc[j][1]));
            rx1 = fmaxf(rx1, fmaxf(sacc[j][2], sacc[j][3]));
        }
#pragma unroll
        for (int off = 1; off <= 2; off <<= 1) {
            rx0 = fmaxf(rx0, __shfl_xor_sync(0xffffffffu, rx0, off));
            rx1 = fmaxf(rx1, __shfl_xor_sync(0xffffffffu, rx1, off));
        }
        float nm0 = fmaxf(m0, rx0 * SCALE), nm1 = fmaxf(m1, rx1 * SCALE);
        float c0 = __expf(m0 - nm0), c1 = __expf(m1 - nm1);
        m0 = nm0; m1 = nm1;

        float ps0 = 0.f, ps1 = 0.f;
        uint32_t pah[4][4], pal[4][4];
#pragma unroll
        for (int t = 0; t < 4; t++) {
#pragma unroll
            for (int jj = 0; jj < 2; jj++) {
                int j = 2 * t + jj;
                float p00 = __expf(fmaf(sacc[j][0], SCALE, -nm0));
                float p01 = __expf(fmaf(sacc[j][1], SCALE, -nm0));
                float p10 = __expf(fmaf(sacc[j][2], SCALE, -nm1));
                float p11 = __expf(fmaf(sacc[j][3], SCALE, -nm1));
                ps0 += p00 + p01;
                ps1 += p10 + p11;
                uint32_t h0 = pack_bf(p00, p01), h1 = pack_bf(p10, p11);
                pah[t][jj * 2]     = h0;
                pah[t][jj * 2 + 1] = h1;
                pal[t][jj * 2]     = pack_bf_lo(p00, p01, h0);
                pal[t][jj * 2 + 1] = pack_bf_lo(p10, p11, h1);
            }
        }
#pragma unroll
        for (int off = 1; off <= 2; off <<= 1) {
            ps0 += __shfl_xor_sync(0xffffffffu, ps0, off);
            ps1 += __shfl_xor_sync(0xffffffffu, ps1, off);
        }
        l0 = l0 * c0 + ps0;
        l1 = l1 * c1 + ps1;
#pragma unroll
        for (int j = 0; j < 8; j++) {
            oacc[j][0] *= c0; oacc[j][1] *= c0;
            oacc[j][2] *= c1; oacc[j][3] *= c1;
        }

        // ---- O += P @ V ----
        const int tt = lane >> 3;
#pragma unroll
        for (int t = 0; t < 4; t++) {
            uint32_t vbh[4][4], vbl[4][4];
#pragma unroll
            for (int g = 0; g < 4; g++) {
                uint32_t off = (t * 16 + (lane & 7) + (tt >> 1) * 8) * 128
                               + g * 32 + (tt & 1) * 16;
                ldsm_x4_t(vbh[g], stg + AV_H + SW128(off));
                ldsm_x4_t(vbl[g], stg + AV_L + SW128(off));
            }
#pragma unroll
            for (int g = 0; g < 4; g++)
#pragma unroll
                for (int nt = 0; nt < 2; nt++)
                    mma_bf16(oacc[g * 2 + nt], pah[t], vbh[g][nt], vbh[g][2 + nt]);
#pragma unroll
            for (int g = 0; g < 4; g++)
#pragma unroll
                for (int nt = 0; nt < 2; nt++)
                    mma_bf16(oacc[g * 2 + nt], pah[t], vbl[g][nt], vbl[g][2 + nt]);
#pragma unroll
            for (int g = 0; g < 4; g++)
#pragma unroll
                for (int nt = 0; nt < 2; nt++)
                    mma_bf16(oacc[g * 2 + nt], pal[t], vbh[g][nt], vbh[g][2 + nt]);
        }
    }
#undef AT_ISSUE

    const float inv0 = 1.f / l0, inv1 = 1.f / l1;
    const int r0g = q0 + w * 16 + (lane >> 2);
    const int r1g = r0g + 8;
    const int cbase = h * DH + (lane & 3) * 2;
#pragma unroll
    for (int j = 0; j < 8; j++) {
        const int col = cbase + j * 8;
        store_split(aoh, aol, ((size_t)b * NQ + r0g) * INNER + col,
                    oacc[j][0] * inv0, oacc[j][1] * inv0);
        store_split(aoh, aol, ((size_t)b * NQ + r1g) * INNER + col,
                    oacc[j][2] * inv1, oacc[j][3] * inv1);
    }
}

// ---------------------------------------------------------------------------
// One fused fp32 -> bf16 hi/lo split over x, ctx, and all 4 weights (natural)
// ---------------------------------------------------------------------------
#define N4_X  (B_ * NQ * DQ / 4)
#define N4_C  (B_ * NK * DC / 4)
#define N4_WQ (DQ * INNER / 4)
#define N4_WK (DC * INNER / 4)
#define N4_WV (DC * INNER / 4)
#define N4_WO (INNER * DQ / 4)
#define C1_ (N4_X)
#define C2_ (C1_ + N4_C)
#define C3_ (C2_ + N4_WQ)
#define C4_ (C3_ + N4_WK)
#define C5_ (C4_ + N4_WV)
#define C6_ (C5_ + N4_WO)

__global__ void split_all(const float4* __restrict__ x, const float4* __restrict__ ctx,
                          const float4* __restrict__ wq, const float4* __restrict__ wk,
                          const float4* __restrict__ wv, const float4* __restrict__ wo)
{
    int i = blockIdx.x * blockDim.x + threadIdx.x;
    if (i >= C6_) return;
    const float4* in;
    __nv_bfloat162 *hi, *lo;
    int idx;
    if      (i < C1_) { in = x;   hi = (__nv_bfloat162*)g_x_hi; lo = (__nv_bfloat162*)g_x_lo; idx = i; }
    else if (i < C2_) { in = ctx; hi = (__nv_bfloat162*)g_c_hi; lo = (__nv_bfloat162*)g_c_lo; idx = i - C1_; }
    else if (i < C3_) { in = wq;  hi = (__nv_bfloat162*)g_wq_hi; lo = (__nv_bfloat162*)g_wq_lo; idx = i - C2_; }
    else if (i < C4_) { in = wk;  hi = (__nv_bfloat162*)g_wk_hi; lo = (__nv_bfloat162*)g_wk_lo; idx = i - C3_; }
    else if (i < C5_) { in = wv;  hi = (__nv_bfloat162*)g_wv_hi; lo = (__nv_bfloat162*)g_wv_lo; idx = i - C4_; }
    else              { in = wo;  hi = (__nv_bfloat162*)g_wo_hi; lo = (__nv_bfloat162*)g_wo_lo; idx = i - C5_; }
    float4 v = in[idx];
    __nv_bfloat16 h0 = __float2bfloat16(v.x), h1 = __float2bfloat16(v.y);
    __nv_bfloat16 h2 = __float2bfloat16(v.z), h3 = __float2bfloat16(v.w);
    hi[2 * idx]     = __halves2bfloat162(h0, h1);
    hi[2 * idx + 1] = __halves2bfloat162(h2, h3);
    lo[2 * idx]     = __halves2bfloat162(
        __float2bfloat16(v.x - __bfloat162float(h0)),
        __float2bfloat16(v.y - __bfloat162float(h1)));
    lo[2 * idx + 1] = __halves2bfloat162(
        __float2bfloat16(v.z - __bfloat162float(h2)),
        __float2bfloat16(v.w - __bfloat162float(h3)));
}

// ---------------------------------------------------------------------------
// Launch: split(0), gemmQ(1), gemmKV(2), attn(3) <- ncu slot, gemmO(4)
// ---------------------------------------------------------------------------
extern "C" void kernel_launch(void* const* d_in, const int* in_sizes, int n_in,
                              void* d_out, int out_size)
{
    const float* x   = (const float*)d_in[0];
    const float* ctx = (const float*)d_in[1];
    const float* Wq  = (const float*)d_in[2];
    const float* Wk  = (const float*)d_in[3];
    const float* Wv  = (const float*)d_in[4];
    const float* Wo  = (const float*)d_in[5];
    const float* bo  = (const float*)d_in[6];
    float* out = (float*)d_out;

    __nv_bfloat16 *xh, *xl, *ch, *cl;
    __nv_bfloat16 *qhp, *qlp, *khp, *klp, *vhp, *vlp, *aoh, *aol;
    __nv_bfloat16 *wqh, *wql, *wkh, *wkl, *wvh, *wvl, *woh, *wol;
    cudaGetSymbolAddress((void**)&xh,  g_x_hi);  cudaGetSymbolAddress((void**)&xl,  g_x_lo);
    cudaGetSymbolAddress((void**)&ch,  g_c_hi);  cudaGetSymbolAddress((void**)&cl,  g_c_lo);
    cudaGetSymbolAddress((void**)&qhp, g_q_hi);  cudaGetSymbolAddress((void**)&qlp, g_q_lo);
    cudaGetSymbolAddress((void**)&khp, g_k_hi);  cudaGetSymbolAddress((void**)&klp, g_k_lo);
    cudaGetSymbolAddress((void**)&vhp, g_v_hi);  cudaGetSymbolAddress((void**)&vlp, g_v_lo);
    cudaGetSymbolAddress((void**)&aoh, g_ao_hi); cudaGetSymbolAddress((void**)&aol, g_ao_lo);
    cudaGetSymbolAddress((void**)&wqh, g_wq_hi); cudaGetSymbolAddress((void**)&wql, g_wq_lo);
    cudaGetSymbolAddress((void**)&wkh, g_wk_hi); cudaGetSymbolAddress((void**)&wkl, g_wk_lo);
    cudaGetSymbolAddress((void**)&wvh, g_wv_hi); cudaGetSymbolAddress((void**)&wvl, g_wv_lo);
    cudaGetSymbolAddress((void**)&woh, g_wo_hi); cudaGetSymbolAddress((void**)&wol, g_wo_lo);

    cudaFuncSetAttribute(mma_gemm<0>, cudaFuncAttributeMaxDynamicSharedMemorySize, GEMM_SMEM);
    cudaFuncSetAttribute(mma_gemm<1>, cudaFuncAttributeMaxDynamicSharedMemorySize, GEMM_SMEM);
    cudaFuncSetAttribute(attn_mma, cudaFuncAttributeMaxDynamicSharedMemorySize, ATTN_SMEM);

    // 0: all splits
    split_all<<<(C6_ + 255) / 256, 256>>>(
        (const float4*)x, (const float4*)ctx, (const float4*)Wq,
        (const float4*)Wk, (const float4*)Wv, (const float4*)Wo);

    // 1: Q projection
    mma_gemm<0><<<dim3(INNER / 128, (B_ * NQ) / 128, 1), 512, GEMM_SMEM>>>(
        xh, xl, wqh, wql, qhp, qlp, wqh, wql, qhp, qlp,
        nullptr, nullptr, B_ * NQ, INNER, DQ);

    // 2: fused K+V projections
    mma_gemm<0><<<dim3(INNER / 128, (B_ * NK) / 128, 2), 512, GEMM_SMEM>>>(
        ch, cl, wkh, wkl, khp, klp, wvh, wvl, vhp, vlp,
        nullptr, nullptr, B_ * NK, INNER, DC);

    // 3: attention (ncu capture slot)
    attn_mma<<<dim3(NQ / 128, HEADS, B_), 256, ATTN_SMEM>>>(
        qhp, qlp, khp, klp, vhp, vlp, aoh, aol);

    // 4: output projection -> fp32 + bias
    mma_gemm<1><<<dim3(DQ / 128, (B_ * NQ) / 128, 1), 512, GEMM_SMEM>>>(
        aoh, aol, woh, wol, nullptr, nullptr, woh, wol, nullptr, nullptr,
        bo, out, B_ * NQ, DQ, INNER);
}

// round 10
// speedup vs baseline: 7.2912x; 2.6445x over previous
#include <cuda_runtime.h>
#include <cuda_fp16.h>
#include <cstdint>

// Problem constants
#define B_     4
#define NQ     2048
#define DQ     1024
#define NK     1024
#define DC     768
#define HEADS  16
#define DH     64
#define INNER  1024   // HEADS*DH

// ---------------------------------------------------------------------------
// Device scratch (static globals). Single fp16 everywhere. Weights natural [K,N].
// ---------------------------------------------------------------------------
__device__ __half g_x [(size_t)B_ * NQ * DQ];
__device__ __half g_c [(size_t)B_ * NK * DC];
__device__ __half g_q [(size_t)B_ * NQ * INNER];
__device__ __half g_k [(size_t)B_ * NK * INNER];
__device__ __half g_v [(size_t)B_ * NK * INNER];
__device__ __half g_ao[(size_t)B_ * NQ * INNER];
__device__ __half g_wq[(size_t)DQ * INNER];
__device__ __half g_wk[(size_t)DC * INNER];
__device__ __half g_wv[(size_t)DC * INNER];
__device__ __half g_wo[(size_t)INNER * DQ];

// ---------------------------------------------------------------------------
// PTX helpers (sm_80-era only: cp.async, ldmatrix, mma.sync)
// ---------------------------------------------------------------------------
__device__ __forceinline__ uint32_t smem_u32(const void* p) {
    uint32_t a;
    asm("{ .reg .u64 t; cvta.to.shared.u64 t, %1; cvt.u32.u64 %0, t; }"
        : "=r"(a) : "l"(p));
    return a;
}
__device__ __forceinline__ void cp_async16(uint32_t s, const void* g) {
    asm volatile("cp.async.cg.shared.global [%0], [%1], 16;" :: "r"(s), "l"(g));
}
__device__ __forceinline__ void ldsm_x4(uint32_t* r, uint32_t a) {
    asm volatile("ldmatrix.sync.aligned.m8n8.x4.shared.b16 {%0,%1,%2,%3}, [%4];"
                 : "=r"(r[0]), "=r"(r[1]), "=r"(r[2]), "=r"(r[3]) : "r"(a));
}
__device__ __forceinline__ void ldsm_x4_t(uint32_t* r, uint32_t a) {
    asm volatile("ldmatrix.sync.aligned.m8n8.x4.trans.shared.b16 {%0,%1,%2,%3}, [%4];"
                 : "=r"(r[0]), "=r"(r[1]), "=r"(r[2]), "=r"(r[3]) : "r"(a));
}
__device__ __forceinline__ void mma_f16(float* d, const uint32_t a[4],
                                        uint32_t b0, uint32_t b1) {
    asm volatile(
        "mma.sync.aligned.m16n8k16.row.col.f32.f16.f16.f32 "
        "{%0,%1,%2,%3}, {%4,%5,%6,%7}, {%8,%9}, {%0,%1,%2,%3};"
        : "+f"(d[0]), "+f"(d[1]), "+f"(d[2]), "+f"(d[3])
        : "r"(a[0]), "r"(a[1]), "r"(a[2]), "r"(a[3]), "r"(b0), "r"(b1));
}
#define SW64(o)  ((o) ^ (((o) >> 3) & 0x30))
#define SW128(o) ((o) ^ (((o) >> 3) & 0x70))
#define CP_COMMIT() asm volatile("cp.async.commit_group;" ::: "memory")
#define CP_WAIT0()  asm volatile("cp.async.wait_group 0;" ::: "memory")
#define CP_WAIT1()  asm volatile("cp.async.wait_group 1;" ::: "memory")

__device__ __forceinline__ uint32_t pack_h(float a, float b) {
    __half2 t = __floats2half2_rn(a, b);
    return *(uint32_t*)&t;
}

// ---------------------------------------------------------------------------
// fp16 GEMM: C = A[M,K] @ W[K,N]. W natural [K,N], B-frags via ldmatrix.trans.
// CTA 128x128x32, 512 thr (16 warps 4x4), warp 32x32, 3-stage ring, 48 KB,
// 2 CTAs/SM. MODE 0: fused QKV (z selects A/W/C); MODE 1: f32 + bias out.
// ---------------------------------------------------------------------------
#define GSTAGE_B  16384                // A(8K) B(8K)
#define GEMM_SMEM (3 * GSTAGE_B)       // 48 KB

template <int MODE>
__global__ __launch_bounds__(512, 2)
void mma_gemm(const __half* __restrict__ Ax, const __half* __restrict__ Ac,
              const __half* __restrict__ W0, const __half* __restrict__ W1,
              const __half* __restrict__ W2,
              __half* __restrict__ C0, __half* __restrict__ C1,
              __half* __restrict__ C2,
              const float* __restrict__ bias, float* __restrict__ Cf)
{
    const int z = blockIdx.z;
    const bool active = !(MODE == 0 && z > 0 && blockIdx.y >= (B_ * NK) / 128);
    if (!active) return;   // uniform per-CTA: all threads exit before any sync

    extern __shared__ __align__(1024) char smraw[];
    const uint32_t sb = smem_u32(smraw);
    const int tid  = threadIdx.x;
    const int wid  = tid >> 5, lane = tid & 31;
    const int wm   = wid & 3,  wn   = wid >> 2;     // 4 x 4 warp grid
    const int row0 = blockIdx.y * 128, col0 = blockIdx.x * 128;
    const int lsel = lane & 15;
    const int khf  = (lane >> 4) * 16;
    const int tt   = lane >> 3;

    const __half* A;
    const __half* W;
    __half* Ch;
    int K;
    if (MODE == 1) {
        A = Ax; W = W0; Ch = nullptr; K = INNER;
    } else if (z == 0) {
        A = Ax; W = W0; Ch = C0; K = DQ;
    } else if (z == 1) {
        A = Ac; W = W1; Ch = C1; K = DC;
    } else {
        A = Ac; W = W2; Ch = C2; K = DC;
    }
    const int N = 1024;
    const int nch = K >> 5;

    float acc[2][4][4];
#pragma unroll
    for (int i = 0; i < 2; i++)
#pragma unroll
        for (int j = 0; j < 4; j++)
#pragma unroll
            for (int q = 0; q < 4; q++) acc[i][j][q] = 0.f;

    const __half* aT = A + (size_t)row0 * K;

#define GISSUE(c)                                                              \
    do {                                                                       \
        const uint32_t stg_ = sb + ((c) % 3) * GSTAGE_B;                       \
        const int k0_ = (c) << 5;                                              \
        /* A: 128 rows x 64B (512 f4) */                                       \
        {                                                                      \
            const int cc = tid;                                                \
            const int r = cc >> 2, cl = cc & 3;                                \
            const uint32_t off = r * 64 + cl * 16;                             \
            cp_async16(stg_ + SW64(off), aT + (size_t)r * K + k0_ + cl * 8);   \
        }                                                                      \
        /* B: 32 rows x 256B, two 64-col halves (512 f4) */                    \
        {                                                                      \
            const int cc = tid;                                                \
            const int half = cc >> 8;                                          \
            const int c2 = cc & 255;                                           \
            const int r = c2 >> 3, seg = c2 & 7;                               \
            const uint32_t off = r * 128 + seg * 16;                           \
            cp_async16(stg_ + 8192 + half * 4096 + SW128(off),                 \
                       W + (size_t)(k0_ + r) * N + col0 + half * 64 + seg * 8);\
        }                                                                      \
        CP_COMMIT();                                                           \
    } while (0)

    GISSUE(0);
    GISSUE(1);
    for (int c = 0; c < nch; c++) {
        if (c + 1 < nch) { CP_WAIT1(); } else { CP_WAIT0(); }
        __syncthreads();
        if (c + 2 < nch) GISSUE(c + 2);

        const uint32_t stg = sb + (c % 3) * GSTAGE_B;
#pragma unroll
        for (int ks = 0; ks < 2; ks++) {
            uint32_t af[2][4], bf[2][4];
#pragma unroll
            for (int mt = 0; mt < 2; mt++) {
                const uint32_t off = (wm * 32 + mt * 16 + lsel) * 64 + ks * 32 + khf;
                ldsm_x4(af[mt], stg + SW64(off));
            }
#pragma unroll
            for (int gg = 0; gg < 2; gg++) {
                const int g = (wn & 1) * 2 + gg;
                const uint32_t off = (ks * 16 + (lane & 7) + ((tt >> 1) << 3)) * 128
                                     + g * 32 + (tt & 1) * 16;
                const uint32_t sw = SW128(off) + (wn >> 1) * 4096;
                ldsm_x4_t(bf[gg], stg + 8192 + sw);
            }
#pragma unroll
            for (int gg = 0; gg < 2; gg++)
#pragma unroll
                for (int mt = 0; mt < 2; mt++)
#pragma unroll
                    for (int nt = 0; nt < 2; nt++)
                        mma_f16(acc[mt][gg * 2 + nt], af[mt], bf[gg][nt], bf[gg][2 + nt]);
        }
    }
#undef GISSUE

    const int rb = row0 + wm * 32 + (lane >> 2);
    const int cb = col0 + wn * 32 + (lane & 3) * 2;
#pragma unroll
    for (int mt = 0; mt < 2; mt++) {
#pragma unroll
        for (int j = 0; j < 4; j++) {
            const int col = cb + j * 8;
            const int r0 = rb + mt * 16;
            float d0 = acc[mt][j][0], d1 = acc[mt][j][1];
            float d2 = acc[mt][j][2], d3 = acc[mt][j][3];
            if (MODE == 1) {
                float b0 = bias[col], b1 = bias[col + 1];
                *(float2*)(Cf + (size_t)r0 * N + col)       = make_float2(d0 + b0, d1 + b1);
                *(float2*)(Cf + (size_t)(r0 + 8) * N + col) = make_float2(d2 + b0, d3 + b1);
            } else {
                *(uint32_t*)(Ch + (size_t)r0 * N + col)       = pack_h(d0, d1);
                *(uint32_t*)(Ch + (size_t)(r0 + 8) * N + col) = pack_h(d2, d3);
            }
        }
    }
}

// ---------------------------------------------------------------------------
// Flash attention via fp16 mma.sync single-pass.
// CTA: 128 q-rows x head x batch; 8 warps x 16 rows. 2-stage KV ring, 48 KB.
// ---------------------------------------------------------------------------
#define AQ_OFF   0
#define AR_BASE  16384
#define AR_STAGE 16384
#define AV_OFF   8192
#define ATTN_SMEM (16384 + 2 * 16384)   // 48 KB

__global__ __launch_bounds__(256, 2)
void attn_mma(const __half* __restrict__ qg, const __half* __restrict__ kg,
              const __half* __restrict__ vg, __half* __restrict__ aog)
{
    extern __shared__ __align__(1024) char smraw[];
    const uint32_t sb = smem_u32(smraw);
    const int tid = threadIdx.x, lane = tid & 31, w = tid >> 5;
    const int q0 = blockIdx.x * 128;
    const int h  = blockIdx.y;
    const int b  = blockIdx.z;
    const int lsel = lane & 15;
    const int khf  = (lane >> 4) * 16;
    const float SCALE = 0.125f;

    // Load Q tile [128 x 64] fp16 into smem (row 128B, SW128)
    const size_t qgb = ((size_t)b * NQ + q0) * INNER + h * DH;
#pragma unroll
    for (int j = 0; j < 4; j++) {
        int idx = tid + 256 * j;           // 0..1023
        int r = idx >> 3, seg = idx & 7;
        uint32_t off = r * 128 + seg * 16;
        *(float4*)(smraw + AQ_OFF + SW128(off)) =
            *(const float4*)(qg + qgb + (size_t)r * INNER + seg * 8);
    }

    float oacc[8][4];
#pragma unroll
    for (int j = 0; j < 8; j++)
#pragma unroll
        for (int q = 0; q < 4; q++) oacc[j][q] = 0.f;
    float m0 = -1e30f, m1 = -1e30f, l0 = 0.f, l1 = 0.f;

#define AT_ISSUE(kt)                                                           \
    do {                                                                       \
        const uint32_t stg_ = sb + AR_BASE + ((kt) & 1) * AR_STAGE;            \
        const size_t kvg = ((size_t)b * NK + (kt) * 64) * INNER + h * DH;      \
        _Pragma("unroll")                                                      \
        for (int j = 0; j < 4; j++) {                                          \
            int idx = tid + 256 * j;       /* 0..1023 */                       \
            int buf = idx >> 9;            /* 0:K 1:V */                       \
            int cc  = idx & 511;                                               \
            int r = cc >> 3, seg = cc & 7;                                     \
            uint32_t off = r * 128 + seg * 16;                                 \
            const __half* src = (buf ? vg : kg) + kvg + (size_t)r * INNER + seg * 8; \
            cp_async16(stg_ + buf * 8192 + SW128(off), src);                   \
        }                                                                      \
        CP_COMMIT();                                                           \
    } while (0)

    const int NT = NK / 64;
    AT_ISSUE(0);
    for (int kt = 0; kt < NT; kt++) {
        CP_WAIT0();
        __syncthreads();                 // tile kt visible; prev compute done
        if (kt + 1 < NT) AT_ISSUE(kt + 1);
        const uint32_t stg = sb + AR_BASE + (kt & 1) * AR_STAGE;

        // ---- S = Q @ K^T ----
        float sacc[8][4];
#pragma unroll
        for (int j = 0; j < 8; j++)
#pragma unroll
            for (int q = 0; q < 4; q++) sacc[j][q] = 0.f;

#pragma unroll
        for (int ks = 0; ks < 4; ks++) {
            uint32_t qf[4];
            {
                uint32_t off = (w * 16 + lsel) * 128 + ks * 32 + khf;
                ldsm_x4(qf, sb + AQ_OFF + SW128(off));
            }
#pragma unroll
            for (int g = 0; g < 4; g++) {
                uint32_t kf[4];
                uint32_t off = (g * 16 + lsel) * 128 + ks * 32 + khf;
                ldsm_x4(kf, stg + SW128(off));
#pragma unroll
                for (int nt = 0; nt < 2; nt++)
                    mma_f16(sacc[g * 2 + nt], qf, kf[nt], kf[2 + nt]);
            }
        }

        // ---- online softmax ----
        float rx0 = -1e30f, rx1 = -1e30f;
#pragma unroll
        for (int j = 0; j < 8; j++) {
            rx0 = fmaxf(rx0, fmaxf(sacc[j][0], sacc[j][1]));
            rx1 = fmaxf(rx1, fmaxf(sacc[j][2], sacc[j][3]));
        }
#pragma unroll
        for (int off = 1; off <= 2; off <<= 1) {
            rx0 = fmaxf(rx0, __shfl_xor_sync(0xffffffffu, rx0, off));
            rx1 = fmaxf(rx1, __shfl_xor_sync(0xffffffffu, rx1, off));
        }
        float nm0 = fmaxf(m0, rx0 * SCALE), nm1 = fmaxf(m1, rx1 * SCALE);
        float c0 = __expf(m0 - nm0), c1 = __expf(m1 - nm1);
        m0 = nm0; m1 = nm1;

        float ps0 = 0.f, ps1 = 0.f;
        uint32_t pa[4][4];
#pragma unroll
        for (int t = 0; t < 4; t++) {
#pragma unroll
            for (int jj = 0; jj < 2; jj++) {
                int j = 2 * t + jj;
                float p00 = __expf(fmaf(sacc[j][0], SCALE, -nm0));
                float p01 = __expf(fmaf(sacc[j][1], SCALE, -nm0));
                float p10 = __expf(fmaf(sacc[j][2], SCALE, -nm1));
                float p11 = __expf(fmaf(sacc[j][3], SCALE, -nm1));
                ps0 += p00 + p01;
                ps1 += p10 + p11;
                pa[t][jj * 2]     = pack_h(p00, p01);
                pa[t][jj * 2 + 1] = pack_h(p10, p11);
            }
        }
#pragma unroll
        for (int off = 1; off <= 2; off <<= 1) {
            ps0 += __shfl_xor_sync(0xffffffffu, ps0, off);
            ps1 += __shfl_xor_sync(0xffffffffu, ps1, off);
        }
        l0 = l0 * c0 + ps0;
        l1 = l1 * c1 + ps1;
#pragma unroll
        for (int j = 0; j < 8; j++) {
            oacc[j][0] *= c0; oacc[j][1] *= c0;
            oacc[j][2] *= c1; oacc[j][3] *= c1;
        }

        // ---- O += P @ V ----
        const int tt = lane >> 3;
#pragma unroll
        for (int t = 0; t < 4; t++) {
#pragma unroll
            for (int g = 0; g < 4; g++) {
                uint32_t vf[4];
                uint32_t off = (t * 16 + (lane & 7) + (tt >> 1) * 8) * 128
                               + g * 32 + (tt & 1) * 16;
                ldsm_x4_t(vf, stg + AV_OFF + SW128(off));
#pragma unroll
                for (int nt = 0; nt < 2; nt++)
                    mma_f16(oacc[g * 2 + nt], pa[t], vf[nt], vf[2 + nt]);
            }
        }
    }
#undef AT_ISSUE

    const float inv0 = 1.f / l0, inv1 = 1.f / l1;
    const int r0g = q0 + w * 16 + (lane >> 2);
    const int r1g = r0g + 8;
    const int cbase = h * DH + (lane & 3) * 2;
#pragma unroll
    for (int j = 0; j < 8; j++) {
        const int col = cbase + j * 8;
        *(uint32_t*)(aog + ((size_t)b * NQ + r0g) * INNER + col) =
            pack_h(oacc[j][0] * inv0, oacc[j][1] * inv0);
        *(uint32_t*)(aog + ((size_t)b * NQ + r1g) * INNER + col) =
            pack_h(oacc[j][2] * inv1, oacc[j][3] * inv1);
    }
}

// ---------------------------------------------------------------------------
// One fused fp32 -> fp16 convert over x, ctx, and all 4 weights
// ---------------------------------------------------------------------------
#define N4_X  (B_ * NQ * DQ / 4)
#define N4_C  (B_ * NK * DC / 4)
#define N4_WQ (DQ * INNER / 4)
#define N4_WK (DC * INNER / 4)
#define N4_WV (DC * INNER / 4)
#define N4_WO (INNER * DQ / 4)
#define C1_ (N4_X)
#define C2_ (C1_ + N4_C)
#define C3_ (C2_ + N4_WQ)
#define C4_ (C3_ + N4_WK)
#define C5_ (C4_ + N4_WV)
#define C6_ (C5_ + N4_WO)

__global__ void cvt_all(const float4* __restrict__ x, const float4* __restrict__ ctx,
                        const float4* __restrict__ wq, const float4* __restrict__ wk,
                        const float4* __restrict__ wv, const float4* __restrict__ wo)
{
    int i = blockIdx.x * blockDim.x + threadIdx.x;
    if (i >= C6_) return;
    const float4* in;
    __half2* dst;
    int idx;
    if      (i < C1_) { in = x;   dst = (__half2*)g_x;  idx = i; }
    else if (i < C2_) { in = ctx; dst = (__half2*)g_c;  idx = i - C1_; }
    else if (i < C3_) { in = wq;  dst = (__half2*)g_wq; idx = i - C2_; }
    else if (i < C4_) { in = wk;  dst = (__half2*)g_wk; idx = i - C3_; }
    else if (i < C5_) { in = wv;  dst = (__half2*)g_wv; idx = i - C4_; }
    else              { in = wo;  dst = (__half2*)g_wo; idx = i - C5_; }
    float4 v = in[idx];
    dst[2 * idx]     = __floats2half2_rn(v.x, v.y);
    dst[2 * idx + 1] = __floats2half2_rn(v.z, v.w);
}

// ---------------------------------------------------------------------------
// Launch: cvt(0), gemmQKV(1), attn(2), gemmO(3) <- ncu slot 3 profiles gemmO
// ---------------------------------------------------------------------------
extern "C" void kernel_launch(void* const* d_in, const int* in_sizes, int n_in,
                              void* d_out, int out_size)
{
    const float* x   = (const float*)d_in[0];
    const float* ctx = (const float*)d_in[1];
    const float* Wq  = (const float*)d_in[2];
    const float* Wk  = (const float*)d_in[3];
    const float* Wv  = (const float*)d_in[4];
    const float* Wo  = (const float*)d_in[5];
    const float* bo  = (const float*)d_in[6];
    float* out = (float*)d_out;

    __half *xp, *cp, *qp, *kp, *vp, *aop, *wqp, *wkp, *wvp, *wop;
    cudaGetSymbolAddress((void**)&xp,  g_x);
    cudaGetSymbolAddress((void**)&cp,  g_c);
    cudaGetSymbolAddress((void**)&qp,  g_q);
    cudaGetSymbolAddress((void**)&kp,  g_k);
    cudaGetSymbolAddress((void**)&vp,  g_v);
    cudaGetSymbolAddress((void**)&aop, g_ao);
    cudaGetSymbolAddress((void**)&wqp, g_wq);
    cudaGetSymbolAddress((void**)&wkp, g_wk);
    cudaGetSymbolAddress((void**)&wvp, g_wv);
    cudaGetSymbolAddress((void**)&wop, g_wo);

    cudaFuncSetAttribute(mma_gemm<0>, cudaFuncAttributeMaxDynamicSharedMemorySize, GEMM_SMEM);
    cudaFuncSetAttribute(mma_gemm<1>, cudaFuncAttributeMaxDynamicSharedMemorySize, GEMM_SMEM);
    cudaFuncSetAttribute(attn_mma, cudaFuncAttributeMaxDynamicSharedMemorySize, ATTN_SMEM);

    // 0: convert all inputs to fp16
    cvt_all<<<(C6_ + 255) / 256, 256>>>(
        (const float4*)x, (const float4*)ctx, (const float4*)Wq,
        (const float4*)Wk, (const float4*)Wv, (const float4*)Wo);

    // 1: fused Q+K+V projections (z: 0=Q over x, 1=K, 2=V over ctx)
    mma_gemm<0><<<dim3(INNER / 128, (B_ * NQ) / 128, 3), 512, GEMM_SMEM>>>(
        xp, cp, wqp, wkp, wvp, qp, kp, vp, nullptr, nullptr);

    // 2: attention
    attn_mma<<<dim3(NQ / 128, HEADS, B_), 256, ATTN_SMEM>>>(qp, kp, vp, aop);

    // 3: output projection -> fp32 + bias  (ncu capture slot)
    mma_gemm<1><<<dim3(DQ / 128, (B_ * NQ) / 128, 1), 512, GEMM_SMEM>>>(
        aop, nullptr, wop, nullptr, nullptr, nullptr, nullptr, nullptr,
        bo, out);
}

// round 12
// speedup vs baseline: 7.3724x; 1.0111x over previous
#include <cuda_runtime.h>
#include <cuda_fp16.h>
#include <cstdint>

// Problem constants
#define B_     4
#define NQ     2048
#define DQ     1024
#define NK     1024
#define DC     768
#define HEADS  16
#define DH     64
#define INNER  1024   // HEADS*DH

// ---------------------------------------------------------------------------
// Device scratch (static globals). Single fp16 everywhere. Weights natural [K,N].
// ---------------------------------------------------------------------------
__device__ __half g_x [(size_t)B_ * NQ * DQ];
__device__ __half g_c [(size_t)B_ * NK * DC];
__device__ __half g_q [(size_t)B_ * NQ * INNER];
__device__ __half g_k [(size_t)B_ * NK * INNER];
__device__ __half g_v [(size_t)B_ * NK * INNER];
__device__ __half g_ao[(size_t)B_ * NQ * INNER];
__device__ __half g_wq[(size_t)DQ * INNER];
__device__ __half g_wk[(size_t)DC * INNER];
__device__ __half g_wv[(size_t)DC * INNER];
__device__ __half g_wo[(size_t)INNER * DQ];

// ---------------------------------------------------------------------------
// PTX helpers (sm_80-era only: cp.async, ldmatrix, mma.sync)
// ---------------------------------------------------------------------------
__device__ __forceinline__ uint32_t smem_u32(const void* p) {
    uint32_t a;
    asm("{ .reg .u64 t; cvta.to.shared.u64 t, %1; cvt.u32.u64 %0, t; }"
        : "=r"(a) : "l"(p));
    return a;
}
__device__ __forceinline__ void cp_async16(uint32_t s, const void* g) {
    asm volatile("cp.async.cg.shared.global [%0], [%1], 16;" :: "r"(s), "l"(g));
}
__device__ __forceinline__ void ldsm_x4(uint32_t* r, uint32_t a) {
    asm volatile("ldmatrix.sync.aligned.m8n8.x4.shared.b16 {%0,%1,%2,%3}, [%4];"
                 : "=r"(r[0]), "=r"(r[1]), "=r"(r[2]), "=r"(r[3]) : "r"(a));
}
__device__ __forceinline__ void ldsm_x4_t(uint32_t* r, uint32_t a) {
    asm volatile("ldmatrix.sync.aligned.m8n8.x4.trans.shared.b16 {%0,%1,%2,%3}, [%4];"
                 : "=r"(r[0]), "=r"(r[1]), "=r"(r[2]), "=r"(r[3]) : "r"(a));
}
__device__ __forceinline__ void mma_f16(float* d, const uint32_t a[4],
                                        uint32_t b0, uint32_t b1) {
    asm volatile(
        "mma.sync.aligned.m16n8k16.row.col.f32.f16.f16.f32 "
        "{%0,%1,%2,%3}, {%4,%5,%6,%7}, {%8,%9}, {%0,%1,%2,%3};"
        : "+f"(d[0]), "+f"(d[1]), "+f"(d[2]), "+f"(d[3])
        : "r"(a[0]), "r"(a[1]), "r"(a[2]), "r"(a[3]), "r"(b0), "r"(b1));
}
#define SW64(o)  ((o) ^ (((o) >> 3) & 0x30))
#define SW128(o) ((o) ^ (((o) >> 3) & 0x70))
#define CP_COMMIT() asm volatile("cp.async.commit_group;" ::: "memory")
#define CP_WAIT0()  asm volatile("cp.async.wait_group 0;" ::: "memory")
#define CP_WAIT1()  asm volatile("cp.async.wait_group 1;" ::: "memory")

__device__ __forceinline__ uint32_t pack_h(float a, float b) {
    __half2 t = __floats2half2_rn(a, b);
    return *(uint32_t*)&t;
}

// ---------------------------------------------------------------------------
// fp16 GEMM: C = A[M,K] @ W[K,N]. W natural [K,N], B-frags via ldmatrix.trans.
// CTA 128x128x32, 256 thr (8 warps 4x2), warp tile 32x64 (16 MMAs / 6 LDSM
// per k-step), 3-stage ring, 48 KB, 2 CTAs/SM.
// MODE 0: fused QKV (z selects A/W/C); MODE 1: f32 + bias out.
// ---------------------------------------------------------------------------
#define GSTAGE_B  16384                // A(8K) B(8K)
#define GEMM_SMEM (3 * GSTAGE_B)       // 48 KB

template <int MODE>
__global__ __launch_bounds__(256, 2)
void mma_gemm(const __half* __restrict__ Ax, const __half* __restrict__ Ac,
              const __half* __restrict__ W0, const __half* __restrict__ W1,
              const __half* __restrict__ W2,
              __half* __restrict__ C0, __half* __restrict__ C1,
              __half* __restrict__ C2,
              const float* __restrict__ bias, float* __restrict__ Cf)
{
    const int z = blockIdx.z;
    const bool active = !(MODE == 0 && z > 0 && blockIdx.y >= (B_ * NK) / 128);
    if (!active) return;   // uniform per-CTA: all threads exit before any sync

    extern __shared__ __align__(1024) char smraw[];
    const uint32_t sb = smem_u32(smraw);
    const int tid  = threadIdx.x;
    const int wid  = tid >> 5, lane = tid & 31;
    const int wm   = wid & 3,  wn   = wid >> 2;     // 4 x 2 warp grid
    const int row0 = blockIdx.y * 128, col0 = blockIdx.x * 128;
    const int lsel = lane & 15;
    const int khf  = (lane >> 4) * 16;
    const int tt   = lane >> 3;

    const __half* A;
    const __half* W;
    __half* Ch;
    int K;
    if (MODE == 1) {
        A = Ax; W = W0; Ch = nullptr; K = INNER;
    } else if (z == 0) {
        A = Ax; W = W0; Ch = C0; K = DQ;
    } else if (z == 1) {
        A = Ac; W = W1; Ch = C1; K = DC;
    } else {
        A = Ac; W = W2; Ch = C2; K = DC;
    }
    const int N = 1024;
    const int nch = K >> 5;

    float acc[2][8][4];
#pragma unroll
    for (int i = 0; i < 2; i++)
#pragma unroll
        for (int j = 0; j < 8; j++)
#pragma unroll
            for (int q = 0; q < 4; q++) acc[i][j][q] = 0.f;

    const __half* aT = A + (size_t)row0 * K;

#define GISSUE(c)                                                              \
    do {                                                                       \
        const uint32_t stg_ = sb + ((c) % 3) * GSTAGE_B;                       \
        const int k0_ = (c) << 5;                                              \
        /* A: 128 rows x 64B = 512 f4; 2 per thread */                         \
        _Pragma("unroll")                                                      \
        for (int j = 0; j < 2; j++) {                                          \
            const int idx = tid + 256 * j;                                     \
            const int r = idx >> 2, cl = idx & 3;                              \
            const uint32_t off = r * 64 + cl * 16;                             \
            cp_async16(stg_ + SW64(off), aT + (size_t)r * K + k0_ + cl * 8);   \
        }                                                                      \
        /* B: 32 rows x 256B, two 64-col halves = 512 f4; 2 per thread */      \
        _Pragma("unroll")                                                      \
        for (int j = 0; j < 2; j++) {                                          \
            const int idx = tid + 256 * j;                                     \
            const int half = idx >> 8;                                         \
            const int c2 = idx & 255;                                          \
            const int r = c2 >> 3, seg = c2 & 7;                               \
            const uint32_t off = r * 128 + seg * 16;                           \
            cp_async16(stg_ + 8192 + half * 4096 + SW128(off),                 \
                       W + (size_t)(k0_ + r) * N + col0 + half * 64 + seg * 8);\
        }                                                                      \
        CP_COMMIT();                                                           \
    } while (0)

    GISSUE(0);
    GISSUE(1);
    for (int c = 0; c < nch; c++) {
        if (c + 1 < nch) { CP_WAIT1(); } else { CP_WAIT0(); }
        __syncthreads();
        if (c + 2 < nch) GISSUE(c + 2);

        const uint32_t stg = sb + (c % 3) * GSTAGE_B;
#pragma unroll
        for (int ks = 0; ks < 2; ks++) {
            uint32_t af[2][4], bf[4][4];
#pragma unroll
            for (int mt = 0; mt < 2; mt++) {
                const uint32_t off = (wm * 32 + mt * 16 + lsel) * 64 + ks * 32 + khf;
                ldsm_x4(af[mt], stg + SW64(off));
            }
#pragma unroll
            for (int g = 0; g < 4; g++) {
                const uint32_t off = (ks * 16 + (lane & 7) + ((tt >> 1) << 3)) * 128
                                     + g * 32 + (tt & 1) * 16;
                const uint32_t sw = SW128(off) + wn * 4096;
                ldsm_x4_t(bf[g], stg + 8192 + sw);
            }
#pragma unroll
            for (int g = 0; g < 4; g++)
#pragma unroll
                for (int mt = 0; mt < 2; mt++)
#pragma unroll
                    for (int nt = 0; nt < 2; nt++)
                        mma_f16(acc[mt][g * 2 + nt], af[mt], bf[g][nt], bf[g][2 + nt]);
        }
    }
#undef GISSUE

    const int rb = row0 + wm * 32 + (lane >> 2);
    const int cb = col0 + wn * 64 + (lane & 3) * 2;
#pragma unroll
    for (int mt = 0; mt < 2; mt++) {
#pragma unroll
        for (int j = 0; j < 8; j++) {
            const int col = cb + j * 8;
            const int r0 = rb + mt * 16;
            float d0 = acc[mt][j][0], d1 = acc[mt][j][1];
            float d2 = acc[mt][j][2], d3 = acc[mt][j][3];
            if (MODE == 1) {
                float b0 = bias[col], b1 = bias[col + 1];
                *(float2*)(Cf + (size_t)r0 * N + col)       = make_float2(d0 + b0, d1 + b1);
                *(float2*)(Cf + (size_t)(r0 + 8) * N + col) = make_float2(d2 + b0, d3 + b1);
            } else {
                *(uint32_t*)(Ch + (size_t)r0 * N + col)       = pack_h(d0, d1);
                *(uint32_t*)(Ch + (size_t)(r0 + 8) * N + col) = pack_h(d2, d3);
            }
        }
    }
}

// ---------------------------------------------------------------------------
// Flash attention via fp16 mma.sync single-pass (unchanged from round 10).
// CTA: 128 q-rows x head x batch; 8 warps x 16 rows. 2-stage KV ring, 48 KB.
// ---------------------------------------------------------------------------
#define AQ_OFF   0
#define AR_BASE  16384
#define AR_STAGE 16384
#define AV_OFF   8192
#define ATTN_SMEM (16384 + 2 * 16384)   // 48 KB

__global__ __launch_bounds__(256, 2)
void attn_mma(const __half* __restrict__ qg, const __half* __restrict__ kg,
              const __half* __restrict__ vg, __half* __restrict__ aog)
{
    extern __shared__ __align__(1024) char smraw[];
    const uint32_t sb = smem_u32(smraw);
    const int tid = threadIdx.x, lane = tid & 31, w = tid >> 5;
    const int q0 = blockIdx.x * 128;
    const int h  = blockIdx.y;
    const int b  = blockIdx.z;
    const int lsel = lane & 15;
    const int khf  = (lane >> 4) * 16;
    const float SCALE = 0.125f;

    // Load Q tile [128 x 64] fp16 into smem (row 128B, SW128)
    const size_t qgb = ((size_t)b * NQ + q0) * INNER + h * DH;
#pragma unroll
    for (int j = 0; j < 4; j++) {
        int idx = tid + 256 * j;           // 0..1023
        int r = idx >> 3, seg = idx & 7;
        uint32_t off = r * 128 + seg * 16;
        *(float4*)(smraw + AQ_OFF + SW128(off)) =
            *(const float4*)(qg + qgb + (size_t)r * INNER + seg * 8);
    }

    float oacc[8][4];
#pragma unroll
    for (int j = 0; j < 8; j++)
#pragma unroll
        for (int q = 0; q < 4; q++) oacc[j][q] = 0.f;
    float m0 = -1e30f, m1 = -1e30f, l0 = 0.f, l1 = 0.f;

#define AT_ISSUE(kt)                                                           \
    do {                                                                       \
        const uint32_t stg_ = sb + AR_BASE + ((kt) & 1) * AR_STAGE;            \
        const size_t kvg = ((size_t)b * NK + (kt) * 64) * INNER + h * DH;      \
        _Pragma("unroll")                                                      \
        for (int j = 0; j < 4; j++) {                                          \
            int idx = tid + 256 * j;       /* 0..1023 */                       \
            int buf = idx >> 9;            /* 0:K 1:V */                       \
            int cc  = idx & 511;                                               \
            int r = cc >> 3, seg = cc & 7;                                     \
            uint32_t off = r * 128 + seg * 16;                                 \
            const __half* src = (buf ? vg : kg) + kvg + (size_t)r * INNER + seg * 8; \
            cp_async16(stg_ + buf * 8192 + SW128(off), src);                   \
        }                                                                      \
        CP_COMMIT();                                                           \
    } while (0)

    const int NT = NK / 64;
    AT_ISSUE(0);
    for (int kt = 0; kt < NT; kt++) {
        CP_WAIT0();
        __syncthreads();                 // tile kt visible; prev compute done
        if (kt + 1 < NT) AT_ISSUE(kt + 1);
        const uint32_t stg = sb + AR_BASE + (kt & 1) * AR_STAGE;

        // ---- S = Q @ K^T ----
        float sacc[8][4];
#pragma unroll
        for (int j = 0; j < 8; j++)
#pragma unroll
            for (int q = 0; q < 4; q++) sacc[j][q] = 0.f;

#pragma unroll
        for (int ks = 0; ks < 4; ks++) {
            uint32_t qf[4];
            {
                uint32_t off = (w * 16 + lsel) * 128 + ks * 32 + khf;
                ldsm_x4(qf, sb + AQ_OFF + SW128(off));
            }
#pragma unroll
            for (int g = 0; g < 4; g++) {
                uint32_t kf[4];
                uint32_t off = (g * 16 + lsel) * 128 + ks * 32 + khf;
                ldsm_x4(kf, stg + SW128(off));
#pragma unroll
                for (int nt = 0; nt < 2; nt++)
                    mma_f16(sacc[g * 2 + nt], qf, kf[nt], kf[2 + nt]);
            }
        }

        // ---- online softmax ----
        float rx0 = -1e30f, rx1 = -1e30f;
#pragma unroll
        for (int j = 0; j < 8; j++) {
            rx0 = fmaxf(rx0, fmaxf(sacc[j][0], sacc[j][1]));
            rx1 = fmaxf(rx1, fmaxf(sacc[j][2], sacc[j][3]));
        }
#pragma unroll
        for (int off = 1; off <= 2; off <<= 1) {
            rx0 = fmaxf(rx0, __shfl_xor_sync(0xffffffffu, rx0, off));
            rx1 = fmaxf(rx1, __shfl_xor_sync(0xffffffffu, rx1, off));
        }
        float nm0 = fmaxf(m0, rx0 * SCALE), nm1 = fmaxf(m1, rx1 * SCALE);
        float c0 = __expf(m0 - nm0), c1 = __expf(m1 - nm1);
        m0 = nm0; m1 = nm1;

        float ps0 = 0.f, ps1 = 0.f;
        uint32_t pa[4][4];
#pragma unroll
        for (int t = 0; t < 4; t++) {
#pragma unroll
            for (int jj = 0; jj < 2; jj++) {
                int j = 2 * t + jj;
                float p00 = __expf(fmaf(sacc[j][0], SCALE, -nm0));
                float p01 = __expf(fmaf(sacc[j][1], SCALE, -nm0));
                float p10 = __expf(fmaf(sacc[j][2], SCALE, -nm1));
                float p11 = __expf(fmaf(sacc[j][3], SCALE, -nm1));
                ps0 += p00 + p01;
                ps1 += p10 + p11;
                pa[t][jj * 2]     = pack_h(p00, p01);
                pa[t][jj * 2 + 1] = pack_h(p10, p11);
            }
        }
#pragma unroll
        for (int off = 1; off <= 2; off <<= 1) {
            ps0 += __shfl_xor_sync(0xffffffffu, ps0, off);
            ps1 += __shfl_xor_sync(0xffffffffu, ps1, off);
        }
        l0 = l0 * c0 + ps0;
        l1 = l1 * c1 + ps1;
#pragma unroll
        for (int j = 0; j < 8; j++) {
            oacc[j][0] *= c0; oacc[j][1] *= c0;
            oacc[j][2] *= c1; oacc[j][3] *= c1;
        }

        // ---- O += P @ V ----
        const int tt = lane >> 3;
#pragma unroll
        for (int t = 0; t < 4; t++) {
#pragma unroll
            for (int g = 0; g < 4; g++) {
                uint32_t vf[4];
                uint32_t off = (t * 16 + (lane & 7) + (tt >> 1) * 8) * 128
                               + g * 32 + (tt & 1) * 16;
                ldsm_x4_t(vf, stg + AV_OFF + SW128(off));
#pragma unroll
                for (int nt = 0; nt < 2; nt++)
                    mma_f16(oacc[g * 2 + nt], pa[t], vf[nt], vf[2 + nt]);
            }
        }
    }
#undef AT_ISSUE

    const float inv0 = 1.f / l0, inv1 = 1.f / l1;
    const int r0g = q0 + w * 16 + (lane >> 2);
    const int r1g = r0g + 8;
    const int cbase = h * DH + (lane & 3) * 2;
#pragma unroll
    for (int j = 0; j < 8; j++) {
        const int col = cbase + j * 8;
        *(uint32_t*)(aog + ((size_t)b * NQ + r0g) * INNER + col) =
            pack_h(oacc[j][0] * inv0, oacc[j][1] * inv0);
        *(uint32_t*)(aog + ((size_t)b * NQ + r1g) * INNER + col) =
            pack_h(oacc[j][2] * inv1, oacc[j][3] * inv1);
    }
}

// ---------------------------------------------------------------------------
// One fused fp32 -> fp16 convert over x, ctx, and all 4 weights
// ---------------------------------------------------------------------------
#define N4_X  (B_ * NQ * DQ / 4)
#define N4_C  (B_ * NK * DC / 4)
#define N4_WQ (DQ * INNER / 4)
#define N4_WK (DC * INNER / 4)
#define N4_WV (DC * INNER / 4)
#define N4_WO (INNER * DQ / 4)
#define C1_ (N4_X)
#define C2_ (C1_ + N4_C)
#define C3_ (C2_ + N4_WQ)
#define C4_ (C3_ + N4_WK)
#define C5_ (C4_ + N4_WV)
#define C6_ (C5_ + N4_WO)

__global__ void cvt_all(const float4* __restrict__ x, const float4* __restrict__ ctx,
                        const float4* __restrict__ wq, const float4* __restrict__ wk,
                        const float4* __restrict__ wv, const float4* __restrict__ wo)
{
    int i = blockIdx.x * blockDim.x + threadIdx.x;
    if (i >= C6_) return;
    const float4* in;
    __half2* dst;
    int idx;
    if      (i < C1_) { in = x;   dst = (__half2*)g_x;  idx = i; }
    else if (i < C2_) { in = ctx; dst = (__half2*)g_c;  idx = i - C1_; }
    else if (i < C3_) { in = wq;  dst = (__half2*)g_wq; idx = i - C2_; }
    else if (i < C4_) { in = wk;  dst = (__half2*)g_wk; idx = i - C3_; }
    else if (i < C5_) { in = wv;  dst = (__half2*)g_wv; idx = i - C4_; }
    else              { in = wo;  dst = (__half2*)g_wo; idx = i - C5_; }
    float4 v = in[idx];
    dst[2 * idx]     = __floats2half2_rn(v.x, v.y);
    dst[2 * idx + 1] = __floats2half2_rn(v.z, v.w);
}

// ---------------------------------------------------------------------------
// Launch: cvt(0), gemmQKV(1), attn(2), gemmO(3) <- ncu slot 3 profiles gemmO
// ---------------------------------------------------------------------------
extern "C" void kernel_launch(void* const* d_in, const int* in_sizes, int n_in,
                              void* d_out, int out_size)
{
    const float* x   = (const float*)d_in[0];
    const float* ctx = (const float*)d_in[1];
    const float* Wq  = (const float*)d_in[2];
    const float* Wk  = (const float*)d_in[3];
    const float* Wv  = (const float*)d_in[4];
    const float* Wo  = (const float*)d_in[5];
    const float* bo  = (const float*)d_in[6];
    float* out = (float*)d_out;

    __half *xp, *cp, *qp, *kp, *vp, *aop, *wqp, *wkp, *wvp, *wop;
    cudaGetSymbolAddress((void**)&xp,  g_x);
    cudaGetSymbolAddress((void**)&cp,  g_c);
    cudaGetSymbolAddress((void**)&qp,  g_q);
    cudaGetSymbolAddress((void**)&kp,  g_k);
    cudaGetSymbolAddress((void**)&vp,  g_v);
    cudaGetSymbolAddress((void**)&aop, g_ao);
    cudaGetSymbolAddress((void**)&wqp, g_wq);
    cudaGetSymbolAddress((void**)&wkp, g_wk);
    cudaGetSymbolAddress((void**)&wvp, g_wv);
    cudaGetSymbolAddress((void**)&wop, g_wo);

    cudaFuncSetAttribute(mma_gemm<0>, cudaFuncAttributeMaxDynamicSharedMemorySize, GEMM_SMEM);
    cudaFuncSetAttribute(mma_gemm<1>, cudaFuncAttributeMaxDynamicSharedMemorySize, GEMM_SMEM);
    cudaFuncSetAttribute(attn_mma, cudaFuncAttributeMaxDynamicSharedMemorySize, ATTN_SMEM);

    // 0: convert all inputs to fp16
    cvt_all<<<(C6_ + 255) / 256, 256>>>(
        (const float4*)x, (const float4*)ctx, (const float4*)Wq,
        (const float4*)Wk, (const float4*)Wv, (const float4*)Wo);

    // 1: fused Q+K+V projections (z: 0=Q over x, 1=K, 2=V over ctx)
    mma_gemm<0><<<dim3(INNER / 128, (B_ * NQ) / 128, 3), 256, GEMM_SMEM>>>(
        xp, cp, wqp, wkp, wvp, qp, kp, vp, nullptr, nullptr);

    // 2: attention
    attn_mma<<<dim3(NQ / 128, HEADS, B_), 256, ATTN_SMEM>>>(qp, kp, vp, aop);

    // 3: output projection -> fp32 + bias  (ncu capture slot)
    mma_gemm<1><<<dim3(DQ / 128, (B_ * NQ) / 128, 1), 256, GEMM_SMEM>>>(
        aop, nullptr, wop, nullptr, nullptr, nullptr, nullptr, nullptr,
        bo, out);
}